// round 10
// baseline (speedup 1.0000x reference)
#include <cuda_runtime.h>
#include <cuda_fp16.h>
#include <cstdint>

// Problem: N=2048, D=128, k=4, T=0.5.
// rows (queries) = 4096, cols (keys) = 8192.
// sim = norm(z[0:4096]) @ norm(z_all)^T * 2 ; mask non-target diagonals;
// loss = mean(logsumexp - pos). Logits in [-2,2] -> no max subtraction.
//
// f16 inputs (rel_err ~0 validated), fp32 accumulators (faster than f16 acc,
// R7 evidence). A operand = f16(2*log2(e) * zhat) -> acc = 2*log2(e)*sim,
// exp term = ex2(acc), pos = acc*ln2, masked diag subtracts the SAME term.
// This round: 4 CTAs/SM (occ 50%) via 64x1024 CTA tiles + 50KB swizzled SMEM.

#define DIMK 128
#define SCALEA 2.885390081777927f     // 2 * log2(e)
#define LN2F 0.6931471805599453f

// ---------------- device scratch (no allocations allowed) -------------------
__device__ __half g_a16[4096 * 128];   // scaled normalized queries
__device__ __half g_b16[8192 * 128];   // normalized keys
__device__ float g_S[4096 * 8];        // [row][cg] exp-sum partials
__device__ float g_pos[4096 * 8];      // [row][cg] positive logit
__device__ unsigned int g_cnt;         // finalize arrival counter

__device__ __forceinline__ uint32_t smem_u32(const void* p) {
    uint32_t a;
    asm("{ .reg .u64 t; cvta.to.shared.u64 t, %1; cvt.u32.u64 %0, t; }"
        : "=r"(a) : "l"(p));
    return a;
}
__device__ __forceinline__ float ex2(float x) {
    float y;
    asm("ex2.approx.ftz.f32 %0, %1;" : "=f"(y) : "f"(x));
    return y;
}
__device__ __forceinline__ void ldsm_x4(uint32_t* r, uint32_t addr) {
    asm volatile("ldmatrix.sync.aligned.m8n8.x4.shared.b16 {%0,%1,%2,%3}, [%4];"
                 : "=r"(r[0]), "=r"(r[1]), "=r"(r[2]), "=r"(r[3]) : "r"(addr));
}
__device__ __forceinline__ void mma16816(float* c, const uint32_t* a,
                                         uint32_t b0, uint32_t b1) {
    asm volatile(
        "mma.sync.aligned.m16n8k16.row.col.f32.f16.f16.f32 "
        "{%0,%1,%2,%3}, {%4,%5,%6,%7}, {%8,%9}, {%0,%1,%2,%3};"
        : "+f"(c[0]), "+f"(c[1]), "+f"(c[2]), "+f"(c[3])
        : "r"(a[0]), "r"(a[1]), "r"(a[2]), "r"(a[3]), "r"(b0), "r"(b1));
}

#define CP_ASYNC16(sm, gp) \
    asm volatile("cp.async.cg.shared.global [%0], [%1], 16;" :: "r"(sm), "l"(gp))
#define CP_COMMIT() asm volatile("cp.async.commit_group;" ::: "memory")
#define CP_WAIT_ALL() asm volatile("cp.async.wait_all;" ::: "memory")

// ---------------------------------------------------------------------------
// Kernel 1: L2-normalize 8192 rows -> f16 keys; first 4096 also scaled f16
// queries. 4 rows per warp. grid 256 x 256.
// ---------------------------------------------------------------------------
__global__ void normalize_kernel(const float* __restrict__ a1,
                                 const float* __restrict__ a2,
                                 const float* __restrict__ a3,
                                 const float* __restrict__ a4) {
    int w = threadIdx.x >> 5, lane = threadIdx.x & 31;
    int row0 = blockIdx.x * 32 + w * 4;
    float4 v[4];
    float ss[4];
#pragma unroll
    for (int i = 0; i < 4; i++) {
        int row = row0 + i;
        const float* src = (row < 2048) ? a1 : (row < 4096) ? a2
                          : (row < 6144) ? a3 : a4;
        v[i] = *(const float4*)(src + (row & 2047) * DIMK + lane * 4);
        ss[i] = v[i].x * v[i].x + v[i].y * v[i].y + v[i].z * v[i].z + v[i].w * v[i].w;
    }
#pragma unroll
    for (int off = 16; off; off >>= 1) {
#pragma unroll
        for (int i = 0; i < 4; i++) ss[i] += __shfl_xor_sync(~0u, ss[i], off);
    }
#pragma unroll
    for (int i = 0; i < 4; i++) {
        int row = row0 + i;
        float inv = 1.0f / fmaxf(sqrtf(ss[i]), 1e-8f);
        float x = v[i].x * inv, y = v[i].y * inv, z = v[i].z * inv, wv = v[i].w * inv;
        __half2 b0 = __float22half2_rn(make_float2(x, y));
        __half2 b1 = __float22half2_rn(make_float2(z, wv));
        uint2 st;
        st.x = *(uint32_t*)&b0;
        st.y = *(uint32_t*)&b1;
        ((uint2*)(g_b16 + row * DIMK))[lane] = st;
        if (row < 4096) {
            __half2 s0 = __float22half2_rn(make_float2(SCALEA * x, SCALEA * y));
            __half2 s1 = __float22half2_rn(make_float2(SCALEA * z, SCALEA * wv));
            uint2 sa;
            sa.x = *(uint32_t*)&s0;
            sa.y = *(uint32_t*)&s1;
            ((uint2*)(g_a16 + row * DIMK))[lane] = sa;
        }
    }
}

// ---------------------------------------------------------------------------
// Kernel 2: f16 HMMA GEMM (fp32 acc) + fused exp epilogue + last-CTA finalize.
// CTA tile = 64 rows x 1024 cols (16 subtiles of 64 cols), K=128 in one shot.
// 256 threads = 8 warps (2 M x 4 N), warp tile 32 rows x 16 cols / subtile.
// XOR-swizzled SMEM (validated in R8): row r, 16B chunk c at
// r*256 + ((c ^ (r&7))<<4). A 16KB + B 2x16KB + reduce 2KB -> 4 CTAs/SM.
// grid = (64 row tiles, 8 col groups) = 512 CTAs, single wave at 4/SM.
// ---------------------------------------------------------------------------
#define SM_A 0
#define SM_B0 16384
#define SM_B1 32768
#define SM_RED 49152                  // float sRed[3][64], pRed[3][64]
#define SMEM_BYTES (49152 + 2048)

__device__ __forceinline__ void load64(uint32_t sb, int sm_off,
                                       const __half* src, int grow0, int tid) {
#pragma unroll
    for (int it = 0; it < 4; it++) {
        int idx = it * 256 + tid;           // 1024 16B vectors (64 rows x 256B)
        int r = idx >> 4, c = idx & 15;
        CP_ASYNC16(sb + sm_off + r * 256 + ((c ^ (r & 7)) << 4),
                   (const char*)(src + (grow0 + r) * DIMK + c * 8));
    }
}

__global__ void __launch_bounds__(256, 4) sim_kernel(float* __restrict__ out) {
    extern __shared__ char smem[];
    uint32_t sb = smem_u32(smem);
    __shared__ int sLast;
    __shared__ float wsum[8];

    int tid = threadIdx.x;
    int lane = tid & 31;
    int w = tid >> 5;
    int wm = w & 1;        // M warp (rows wm*32..+31)
    int wn = w >> 1;       // N warp (cols wn*16..+15 of the 64-col subtile)
    int row0 = blockIdx.x * 64;
    int cg = blockIdx.y;                  // cols [cg*1024, cg*1024+1024)

    // ---- prologue: A (64 rows) + B subtile 0 (64 rows) ----
    load64(sb, SM_A, g_a16, row0, tid);
    load64(sb, SM_B0, g_b16, cg * 1024, tid);
    CP_COMMIT();

    // ---- ldmatrix lane bases (swizzled) ----
    int arow = wm * 32 + ((lane >> 3) & 1) * 8 + (lane & 7);
    int koctA = lane >> 4;                 // 0/1
    int r7A = arow & 7;
    uint32_t baseA0 = sb + SM_A + arow * 256;
    uint32_t baseA1 = baseA0 + 16 * 256;   // (arow+16)&7 == arow&7

    int brow = wn * 16 + ((lane >> 4) & 1) * 8 + (lane & 7);
    int koctB = (lane >> 3) & 1;
    int r7B = brow & 7;
    uint32_t brOff = brow * 256;

    int qrow = lane >> 2;          // 0..7
    // ---- per-row diagonal bookkeeping ----
    int half = row0 >> 11;
    int cblk = cg >> 1;
    bool tgt = (cblk == 1 - half);
    int dl0 = (row0 & 2047) - (cg & 1) * 1024;

    int dcol[4], rloc[4];
#pragma unroll
    for (int mi = 0; mi < 2; mi++)
#pragma unroll
        for (int h = 0; h < 2; h++) {
            int i = mi * 2 + h;
            rloc[i] = wm * 32 + mi * 16 + qrow + 8 * h;
            dcol[i] = dl0 + rloc[i];       // diag col within CTA's 1024 cols
        }

    float sumReg[4] = {0.f, 0.f, 0.f, 0.f};
    float posReg[4] = {0.f, 0.f, 0.f, 0.f};

    for (int ct = 0; ct < 16; ct++) {
        CP_WAIT_ALL();
        __syncthreads();

        if (ct < 15) {                     // prefetch B(ct+1), overlapped
            load64(sb, ((ct + 1) & 1) ? SM_B1 : SM_B0,
                   g_b16, cg * 1024 + (ct + 1) * 64, tid);
            CP_COMMIT();
        }

        uint32_t bufB = sb + ((ct & 1) ? SM_B1 : SM_B0);

        float acc[2][2][4];                // [mi][n8 frag][c]
#pragma unroll
        for (int mi = 0; mi < 2; mi++)
#pragma unroll
            for (int ni = 0; ni < 2; ni++)
#pragma unroll
                for (int c = 0; c < 4; c++) acc[mi][ni][c] = 0.f;

#pragma unroll
        for (int ks = 0; ks < 8; ks++) {
            uint32_t offA = (uint32_t)(((2 * ks + koctA) ^ r7A) << 4);
            uint32_t offB = (uint32_t)(((2 * ks + koctB) ^ r7B) << 4);
            uint32_t a0[4], a1[4], b[4];
            ldsm_x4(a0, baseA0 + offA);
            ldsm_x4(a1, baseA1 + offA);
            ldsm_x4(b, bufB + brOff + offB);   // n8#0 (klo,khi), n8#1 (klo,khi)
            mma16816(acc[0][0], a0, b[0], b[1]);
            mma16816(acc[0][1], a0, b[2], b[3]);
            mma16816(acc[1][0], a1, b[0], b[1]);
            mma16816(acc[1][1], a1, b[2], b[3]);
        }

        // ---- epilogue: ex2-sum (scale pre-folded into A) + diag fixup ----
#pragma unroll
        for (int mi = 0; mi < 2; mi++)
#pragma unroll
            for (int h = 0; h < 2; h++) {
                int i = mi * 2 + h;
                float s = ex2(acc[mi][0][2 * h + 0]) + ex2(acc[mi][0][2 * h + 1])
                        + ex2(acc[mi][1][2 * h + 0]) + ex2(acc[mi][1][2 * h + 1]);
                sumReg[i] += s;
                int d = dcol[i];
                if ((unsigned)d < 1024u && (d >> 6) == ct
                    && ((d >> 4) & 3) == wn
                    && ((d & 7) >> 1) == (lane & 3)) {
                    int nid = (d & 15) >> 3;
                    float vd = acc[mi][nid][2 * h + (d & 1)];
                    if (tgt) posReg[i] += vd * LN2F;   // pos = acc*ln2
                    else sumReg[i] -= ex2(vd);         // same term: cancel
                }
            }
    }

    // ---- reduce across 4 col-lanes, then across the 4 N warps via SMEM ----
#pragma unroll
    for (int i = 0; i < 4; i++) {
        sumReg[i] += __shfl_xor_sync(~0u, sumReg[i], 1);
        sumReg[i] += __shfl_xor_sync(~0u, sumReg[i], 2);
        posReg[i] += __shfl_xor_sync(~0u, posReg[i], 1);
        posReg[i] += __shfl_xor_sync(~0u, posReg[i], 2);
    }
    float* sRed = (float*)(smem + SM_RED);         // [3][64]
    float* pRed = (float*)(smem + SM_RED + 768);   // [3][64]
    __syncthreads();
    if ((lane & 3) == 0 && wn > 0) {
#pragma unroll
        for (int i = 0; i < 4; i++) {
            sRed[(wn - 1) * 64 + rloc[i]] = sumReg[i];
            pRed[(wn - 1) * 64 + rloc[i]] = posReg[i];
        }
    }
    __syncthreads();
    if ((lane & 3) == 0 && wn == 0) {
#pragma unroll
        for (int i = 0; i < 4; i++) {
            int rl = rloc[i];
            int row = row0 + rl;
            g_S[row * 8 + cg] = sumReg[i] + sRed[rl] + sRed[64 + rl] + sRed[128 + rl];
            g_pos[row * 8 + cg] = posReg[i] + pRed[rl] + pRed[64 + rl] + pRed[128 + rl];
        }
    }

    // ---- last-CTA finalize (deterministic; 512 CTAs) ----
    __threadfence();
    __syncthreads();
    if (tid == 0) sLast = (atomicAdd(&g_cnt, 1u) == 511u);
    __syncthreads();
    if (sLast) {
        __threadfence();   // acquire side
        float local = 0.f;
        for (int r = tid; r < 4096; r += 256) {
            const float4* s4 = (const float4*)(g_S + r * 8);
            const float4* p4 = (const float4*)(g_pos + r * 8);
            float4 x0 = s4[0], x1 = s4[1], y0 = p4[0], y1 = p4[1];
            float S = (x0.x + x0.y) + (x0.z + x0.w) + (x1.x + x1.y) + (x1.z + x1.w);
            float p = (y0.x + y0.y) + (y0.z + y0.w) + (y1.x + y1.y) + (y1.z + y1.w);
            local += logf(S) - p;
        }
#pragma unroll
        for (int off = 16; off; off >>= 1) local += __shfl_xor_sync(~0u, local, off);
        if (lane == 0) wsum[tid >> 5] = local;
        __syncthreads();
        if (tid < 32) {
            float t = (tid < 8) ? wsum[tid] : 0.f;
#pragma unroll
            for (int off = 4; off; off >>= 1) t += __shfl_xor_sync(~0u, t, off);
            if (tid == 0) {
                out[0] = t / 4096.f;
                g_cnt = 0;               // reset for next graph replay
            }
        }
    }
}

// ---------------------------------------------------------------------------
extern "C" void kernel_launch(void* const* d_in, const int* in_sizes, int n_in,
                              void* d_out, int out_size) {
    const float* a1 = (const float*)d_in[0];
    const float* a2 = (const float*)d_in[1];
    const float* a3 = (const float*)d_in[2];
    const float* a4 = (const float*)d_in[3];

    normalize_kernel<<<256, 256>>>(a1, a2, a3, a4);

    cudaFuncSetAttribute(sim_kernel, cudaFuncAttributeMaxDynamicSharedMemorySize,
                         SMEM_BYTES);
    dim3 grid(64, 8);
    sim_kernel<<<grid, 256, SMEM_BYTES>>>((float*)d_out);
}

// round 11
// speedup vs baseline: 1.4766x; 1.4766x over previous
#include <cuda_runtime.h>
#include <cuda_fp16.h>
#include <cstdint>

// Problem: N=2048, D=128, k=4, T=0.5.
// rows (queries) = 4096, cols (keys) = 8192.
// sim = norm(z[0:4096]) @ norm(z_all)^T * 2 ; mask non-target diagonals;
// loss = mean(logsumexp - pos). Logits in [-2,2] -> no max subtraction.
//
// Symmetry: left half (cols 0..4095) is zhat@zhat^T (symmetric). Compute only
// upper-triangle 128x128 tiles; each off-diagonal tile contributes exp-sums to
// BOTH its row block (row reduction) and col block (column reduction).
// Work units: 1024 right-half tiles + 528 left-triangle tiles = 1552 (75.8%).
//
// f16 operands (validated rel_err 0), fp32 acc. A = f16(2*log2(e)*zhat) so
// acc = 2*log2(e)*sim; exp term = ex2(acc); pos = acc*ln2; masked diagonals
// subtract the identical ex2 term (exact cancellation).

#define DIMK 128
#define SCALEA 2.885390081777927f     // 2 * log2(e)
#define LN2F 0.6931471805599453f

// ---------------- device scratch (no allocations allowed) -------------------
__device__ __half g_a16[4096 * 128];   // scaled normalized queries
__device__ __half g_b16[8192 * 128];   // normalized keys (rows 0..4095 == queries)
__device__ float g_S[4096 * 64];       // [row][slot] exp-sum partials (1 writer each)
__device__ float g_pos[4096];          // positive logit per row (1 writer each)
__device__ float g_fin[16];            // finalize partials
__device__ unsigned int g_cnt, g_cnt2, g_flag;

__device__ __forceinline__ uint32_t smem_u32(const void* p) {
    uint32_t a;
    asm("{ .reg .u64 t; cvta.to.shared.u64 t, %1; cvt.u32.u64 %0, t; }"
        : "=r"(a) : "l"(p));
    return a;
}
__device__ __forceinline__ float ex2(float x) {
    float y;
    asm("ex2.approx.ftz.f32 %0, %1;" : "=f"(y) : "f"(x));
    return y;
}
__device__ __forceinline__ void ldsm_x4(uint32_t* r, uint32_t addr) {
    asm volatile("ldmatrix.sync.aligned.m8n8.x4.shared.b16 {%0,%1,%2,%3}, [%4];"
                 : "=r"(r[0]), "=r"(r[1]), "=r"(r[2]), "=r"(r[3]) : "r"(addr));
}
__device__ __forceinline__ void mma16816(float* c, const uint32_t* a,
                                         uint32_t b0, uint32_t b1) {
    asm volatile(
        "mma.sync.aligned.m16n8k16.row.col.f32.f16.f16.f32 "
        "{%0,%1,%2,%3}, {%4,%5,%6,%7}, {%8,%9}, {%0,%1,%2,%3};"
        : "+f"(c[0]), "+f"(c[1]), "+f"(c[2]), "+f"(c[3])
        : "r"(a[0]), "r"(a[1]), "r"(a[2]), "r"(a[3]), "r"(b0), "r"(b1));
}

#define CP_ASYNC16(sm, gp) \
    asm volatile("cp.async.cg.shared.global [%0], [%1], 16;" :: "r"(sm), "l"(gp))
#define CP_COMMIT() asm volatile("cp.async.commit_group;" ::: "memory")
#define CP_WAIT_ALL() asm volatile("cp.async.wait_all;" ::: "memory")

// ---------------------------------------------------------------------------
// Kernel 1: L2-normalize 8192 rows -> f16 keys; first 4096 also scaled queries.
// ---------------------------------------------------------------------------
__global__ void normalize_kernel(const float* __restrict__ a1,
                                 const float* __restrict__ a2,
                                 const float* __restrict__ a3,
                                 const float* __restrict__ a4) {
    int w = threadIdx.x >> 5, lane = threadIdx.x & 31;
    int row0 = blockIdx.x * 32 + w * 4;
    float4 v[4];
    float ss[4];
#pragma unroll
    for (int i = 0; i < 4; i++) {
        int row = row0 + i;
        const float* src = (row < 2048) ? a1 : (row < 4096) ? a2
                          : (row < 6144) ? a3 : a4;
        v[i] = *(const float4*)(src + (row & 2047) * DIMK + lane * 4);
        ss[i] = v[i].x * v[i].x + v[i].y * v[i].y + v[i].z * v[i].z + v[i].w * v[i].w;
    }
#pragma unroll
    for (int off = 16; off; off >>= 1) {
#pragma unroll
        for (int i = 0; i < 4; i++) ss[i] += __shfl_xor_sync(~0u, ss[i], off);
    }
#pragma unroll
    for (int i = 0; i < 4; i++) {
        int row = row0 + i;
        float inv = 1.0f / fmaxf(sqrtf(ss[i]), 1e-8f);
        float x = v[i].x * inv, y = v[i].y * inv, z = v[i].z * inv, wv = v[i].w * inv;
        __half2 b0 = __float22half2_rn(make_float2(x, y));
        __half2 b1 = __float22half2_rn(make_float2(z, wv));
        uint2 st;
        st.x = *(uint32_t*)&b0;
        st.y = *(uint32_t*)&b1;
        ((uint2*)(g_b16 + row * DIMK))[lane] = st;
        if (row < 4096) {
            __half2 s0 = __float22half2_rn(make_float2(SCALEA * x, SCALEA * y));
            __half2 s1 = __float22half2_rn(make_float2(SCALEA * z, SCALEA * wv));
            uint2 sa;
            sa.x = *(uint32_t*)&s0;
            sa.y = *(uint32_t*)&s1;
            ((uint2*)(g_a16 + row * DIMK))[lane] = sa;
        }
    }
}

// ---------------------------------------------------------------------------
// Kernel 2: unit-list GEMM. 256 CTAs (single wave @2/SM), 256 thr = 8 warps
// (4M x 2N), unit = 128x128 tile, warp tile 32x64, K=128 in one shot.
// Unit list: u<1024: right tile (i=u>>5, s=u&31). u>=1024: triangle (i,j), j>=i.
// A cached across units sharing a row block; B double-buffered via cp.async.
// ---------------------------------------------------------------------------
#define TSTRIDE 272
#define SM_A 0
#define SM_B0 34816
#define SM_B1 69632
#define SM_SCR 104448                  // 512 floats scratch
#define SMEM_BYTES 106496

// flags
#define UF_RIGHT 1
#define UF_DIAG  2
#define UF_POS   4
#define UF_OFFD  8

struct Unit {
    int aRow0, bRow0, slotD, slotT, flags, dl0;
};

__device__ __forceinline__ Unit decode_unit(int u) {
    Unit un;
    if (u < 1024) {
        int i = u >> 5, s = u & 31;
        un.aRow0 = i * 128;
        un.bRow0 = 4096 + s * 128;
        un.slotD = 32 + s;
        un.slotT = 0;
        un.flags = UF_RIGHT;
        un.dl0 = (un.aRow0 & 2047) - ((s * 128) & 2047);
        return un;
    }
    int t = u - 1024;
    int i = 0, base = 0;
    while (base + (32 - i) <= t) { base += 32 - i; i++; }
    int j = i + (t - base);
    un.aRow0 = i * 128;
    un.bRow0 = j * 128;
    un.slotD = j;
    un.slotT = i;
    if (i == j) { un.flags = UF_DIAG; un.dl0 = 0; }
    else if (j - i == 16) { un.flags = UF_POS | UF_OFFD; un.dl0 = 0; }
    else { un.flags = UF_OFFD; un.dl0 = -1000000; }
    return un;
}

__device__ __forceinline__ void issue_tile(uint32_t sb, int sm_off,
                                           const __half* src, int grow0, int tid) {
#pragma unroll
    for (int it = 0; it < 8; it++) {
        int idx = it * 256 + tid;           // 2048 16B vectors
        int r = idx >> 4, g = idx & 15;
        CP_ASYNC16(sb + sm_off + r * TSTRIDE + g * 16,
                   (const char*)(src + (grow0 + r) * DIMK + g * 8));
    }
}

__global__ void __launch_bounds__(256, 2) sim_kernel(float* __restrict__ out) {
    extern __shared__ char smem[];
    uint32_t sb = smem_u32(smem);
    float* scr = (float*)(smem + SM_SCR);   // [0,128) rowsum; [128,512) colsum
    __shared__ int sK, sLast2;

    int tid = threadIdx.x;
    int lane = tid & 31;
    int w = tid >> 5;
    int wm = w & 3;        // M warp (rows wm*32..+31)
    int wn = w >> 2;       // N warp (cols wn*64..+63)
    int c = blockIdx.x;    // 0..255

    int start = 6 * c + min(c, 16);
    int cnt = 6 + (c < 16 ? 1 : 0);

    // ldmatrix lane bases (padded-stride layout, proven conflict-free)
    int arow = wm * 32 + ((lane >> 3) & 1) * 8 + (lane & 7);
    int akoct = (lane >> 4) * 8;
    uint32_t baseA = sb + SM_A + arow * TSTRIDE + akoct * 2;
    int brow = wn * 64 + ((lane >> 4) & 1) * 8 + (lane & 7);
    int bkoct = ((lane >> 3) & 1) * 8;
    uint32_t baseBoff = brow * TSTRIDE + bkoct * 2;

    int qrow = lane >> 2;
    int rloc[4];
#pragma unroll
    for (int mi = 0; mi < 2; mi++)
#pragma unroll
        for (int h = 0; h < 2; h++)
            rloc[mi * 2 + h] = wm * 32 + mi * 16 + qrow + 8 * h;

    // prologue
    Unit cur = decode_unit(start);
    issue_tile(sb, SM_A, g_a16, cur.aRow0, tid);
    issue_tile(sb, SM_B0, g_b16, cur.bRow0, tid);
    CP_COMMIT();
    int prevA = cur.aRow0;

    for (int idx = 0; idx < cnt; idx++) {
        Unit nxt;
        bool hasNext = (idx + 1 < cnt);
        if (hasNext) nxt = decode_unit(start + idx + 1);

        if (cur.aRow0 != prevA) {           // uniform condition
            __syncthreads();                // all warps done with old A
            issue_tile(sb, SM_A, g_a16, cur.aRow0, tid);
            CP_COMMIT();
            prevA = cur.aRow0;
        }
        CP_WAIT_ALL();                      // B(cur) (+A if reloaded) ready
        __syncthreads();

        if (hasNext) {                      // prefetch next B, overlapped
            issue_tile(sb, ((idx + 1) & 1) ? SM_B1 : SM_B0, g_b16, nxt.bRow0, tid);
            CP_COMMIT();
        }

        uint32_t baseB = sb + ((idx & 1) ? SM_B1 : SM_B0) + baseBoff;

        float acc[2][8][4];
#pragma unroll
        for (int mi = 0; mi < 2; mi++)
#pragma unroll
            for (int ni = 0; ni < 8; ni++)
#pragma unroll
                for (int q = 0; q < 4; q++) acc[mi][ni][q] = 0.f;

#pragma unroll
        for (int ks = 0; ks < 8; ks++) {
            uint32_t a[2][4];
            ldsm_x4(a[0], baseA + ks * 32);
            ldsm_x4(a[1], baseA + 16 * TSTRIDE + ks * 32);
            uint32_t b[4][4];
#pragma unroll
            for (int nip = 0; nip < 4; nip++)
                ldsm_x4(b[nip], baseB + nip * 16 * TSTRIDE + ks * 32);
#pragma unroll
            for (int mi = 0; mi < 2; mi++)
#pragma unroll
                for (int nip = 0; nip < 4; nip++) {
                    mma16816(acc[mi][2 * nip + 0], a[mi], b[nip][0], b[nip][1]);
                    mma16816(acc[mi][2 * nip + 1], a[mi], b[nip][2], b[nip][3]);
                }
        }

        // ================= epilogue =================
        int fl = cur.flags;
        // save positive logit value BEFORE ex2 overwrite
        float vdPos[4];
        bool ownD[4];
#pragma unroll
        for (int i4 = 0; i4 < 4; i4++) {
            int d = cur.dl0 + rloc[i4];
            ownD[i4] = ((unsigned)d < 128u) && (((d >> 6) & 1) == wn)
                     && (((d & 7) >> 1) == (lane & 3));
            int mi = i4 >> 1, h = i4 & 1;
            int nid = (d & 63) >> 3, cid = 2 * h + (d & 1);
            vdPos[i4] = ownD[i4] ? acc[mi][nid][cid] : 0.f;
        }

        // ex2 overwrite + row sums
        float rsum[4];
#pragma unroll
        for (int mi = 0; mi < 2; mi++)
#pragma unroll
            for (int h = 0; h < 2; h++) {
                float s = 0.f;
#pragma unroll
                for (int ni = 0; ni < 8; ni++) {
#pragma unroll
                    for (int j = 0; j < 2; j++) {
                        float e = ex2(acc[mi][ni][2 * h + j]);
                        acc[mi][ni][2 * h + j] = e;
                        s += e;
                    }
                }
                rsum[mi * 2 + h] = s;
            }
        // masked diagonal: subtract the identical term
        if (fl & (UF_RIGHT | UF_DIAG)) {
#pragma unroll
            for (int i4 = 0; i4 < 4; i4++) {
                if (ownD[i4]) {
                    int d = cur.dl0 + rloc[i4];
                    int mi = i4 >> 1, h = i4 & 1;
                    rsum[i4] -= acc[mi][(d & 63) >> 3][2 * h + (d & 1)];
                }
            }
        }
        // reduce rowsums across 4 col-lanes
#pragma unroll
        for (int i4 = 0; i4 < 4; i4++) {
            rsum[i4] += __shfl_xor_sync(~0u, rsum[i4], 1);
            rsum[i4] += __shfl_xor_sync(~0u, rsum[i4], 2);
        }

        // column sums (symmetric off-diagonal tiles)
        float csum[16];
        if (fl & UF_OFFD) {
#pragma unroll
            for (int ni = 0; ni < 8; ni++)
#pragma unroll
                for (int j = 0; j < 2; j++) {
                    int k = ni * 2 + j;
                    csum[k] = acc[0][ni][j] + acc[0][ni][2 + j]
                            + acc[1][ni][j] + acc[1][ni][2 + j];
                    csum[k] += __shfl_xor_sync(~0u, csum[k], 4);
                    csum[k] += __shfl_xor_sync(~0u, csum[k], 8);
                    csum[k] += __shfl_xor_sync(~0u, csum[k], 16);
                }
        }

        // stage-1 scratch writes
        if (wn == 1 && (lane & 3) == 0) {
#pragma unroll
            for (int i4 = 0; i4 < 4; i4++) scr[rloc[i4]] = rsum[i4];
        }
        if ((fl & UF_OFFD) && wm > 0 && lane < 4) {
#pragma unroll
            for (int k = 0; k < 16; k++) {
                int cl = wn * 64 + (k >> 1) * 8 + lane * 2 + (k & 1);
                scr[128 + (wm - 1) * 128 + cl] = csum[k];
            }
        }
        __syncthreads();
        // stage-2 combine + global writes
        if (wn == 0 && (lane & 3) == 0) {
#pragma unroll
            for (int i4 = 0; i4 < 4; i4++) {
                int row = cur.aRow0 + rloc[i4];
                g_S[row * 64 + cur.slotD] = rsum[i4] + scr[rloc[i4]];
            }
        }
        if ((fl & UF_OFFD) && wm == 0 && lane < 4) {
#pragma unroll
            for (int k = 0; k < 16; k++) {
                int cl = wn * 64 + (k >> 1) * 8 + lane * 2 + (k & 1);
                float tot = csum[k] + scr[128 + cl] + scr[256 + cl] + scr[384 + cl];
                g_S[(cur.bRow0 + cl) * 64 + cur.slotT] = tot;
            }
        }
        if (fl & UF_POS) {
#pragma unroll
            for (int i4 = 0; i4 < 4; i4++) {
                if (ownD[i4]) {
                    int row = cur.aRow0 + rloc[i4];
                    float p = vdPos[i4] * LN2F;
                    g_pos[row] = p;
                    g_pos[row + 2048] = p;    // symmetric partner
                }
            }
        }
        cur = nxt;
    }

    // ================= finalize: last 16 arrivals, gated by arrival #255 ====
    __threadfence();
    __syncthreads();
    if (tid == 0) sK = (int)atomicAdd(&g_cnt, 1u);
    __syncthreads();
    int k = sK;
    if (k >= 240) {
        if (k == 255 && tid == 0) atomicExch(&g_flag, 1u);
        if (tid == 0) while (atomicAdd(&g_flag, 0u) == 0u) { }
        __syncthreads();
        __threadfence();
        int row = (k - 240) * 256 + tid;
        const float4* s4 = (const float4*)(g_S + row * 64);
        float S = 0.f;
#pragma unroll
        for (int q = 0; q < 16; q++) {
            float4 x = s4[q];
            S += (x.x + x.y) + (x.z + x.w);
        }
        float local = logf(S) - g_pos[row];
#pragma unroll
        for (int off = 16; off; off >>= 1) local += __shfl_xor_sync(~0u, local, off);
        __shared__ float wred[8];
        if (lane == 0) wred[tid >> 5] = local;
        __syncthreads();
        if (tid == 0) {
            float t = 0.f;
#pragma unroll
            for (int q = 0; q < 8; q++) t += wred[q];
            g_fin[k - 240] = t;
            __threadfence();
            int k2 = (int)atomicAdd(&g_cnt2, 1u);
            sLast2 = (k2 == 15);
        }
        __syncthreads();
        if (sLast2 && tid == 0) {
            __threadfence();
            float t = 0.f;
#pragma unroll
            for (int q = 0; q < 16; q++) t += g_fin[q];
            out[0] = t / 4096.f;
            g_cnt = 0; g_cnt2 = 0; g_flag = 0;    // reset for graph replay
        }
    }
}

// ---------------------------------------------------------------------------
extern "C" void kernel_launch(void* const* d_in, const int* in_sizes, int n_in,
                              void* d_out, int out_size) {
    const float* a1 = (const float*)d_in[0];
    const float* a2 = (const float*)d_in[1];
    const float* a3 = (const float*)d_in[2];
    const float* a4 = (const float*)d_in[3];

    normalize_kernel<<<256, 256>>>(a1, a2, a3, a4);

    cudaFuncSetAttribute(sim_kernel, cudaFuncAttributeMaxDynamicSharedMemorySize,
                         SMEM_BYTES);
    sim_kernel<<<256, 256, SMEM_BYTES>>>((float*)d_out);
}

// round 12
// speedup vs baseline: 1.7328x; 1.1735x over previous
#include <cuda_runtime.h>
#include <cuda_fp16.h>
#include <cstdint>

// Problem: N=2048, D=128, k=4, T=0.5.
// rows (queries) = 4096, cols (keys) = 8192.
// sim = norm(z[0:4096]) @ norm(z_all)^T * 2 ; mask non-target diagonals;
// loss = mean(logsumexp - pos). Logits in [-2,2] -> no max subtraction.
//
// Recombination of measured-best parts:
//  - R4 GEMM core (fastest measured ~35us): 128x512 CTA tile, grid (32,16),
//    4 subtiles of 128 cols, double-buffered B via cp.async, 8 warps (4Mx2N).
//  - f16 operands, A pre-scaled by 2*log2(e) (R7: rel_err 0; epilogue = ex2).
//  - R5 register-resident row accumulators (no per-subtile smem reduce).
//  - R11 last-16-CTA in-kernel finalize (deletes both tail kernels).

#define DIMK 128
#define SCALEA 2.885390081777927f     // 2 * log2(e)
#define LN2F 0.6931471805599453f

// ---------------- device scratch (no allocations allowed) -------------------
__device__ __half g_a16[4096 * 128];   // scaled normalized queries
__device__ __half g_b16[8192 * 128];   // normalized keys
__device__ float g_S[4096 * 16];       // [row][cg] exp-sum partials
__device__ float g_pos[4096 * 16];     // [row][cg] positive logit
__device__ float g_fin[16];            // finalize partials
__device__ unsigned int g_cnt, g_cnt2, g_flag;

__device__ __forceinline__ uint32_t smem_u32(const void* p) {
    uint32_t a;
    asm("{ .reg .u64 t; cvta.to.shared.u64 t, %1; cvt.u32.u64 %0, t; }"
        : "=r"(a) : "l"(p));
    return a;
}
__device__ __forceinline__ float ex2(float x) {
    float y;
    asm("ex2.approx.ftz.f32 %0, %1;" : "=f"(y) : "f"(x));
    return y;
}
__device__ __forceinline__ void ldsm_x4(uint32_t* r, uint32_t addr) {
    asm volatile("ldmatrix.sync.aligned.m8n8.x4.shared.b16 {%0,%1,%2,%3}, [%4];"
                 : "=r"(r[0]), "=r"(r[1]), "=r"(r[2]), "=r"(r[3]) : "r"(addr));
}
__device__ __forceinline__ void mma16816(float* c, const uint32_t* a,
                                         uint32_t b0, uint32_t b1) {
    asm volatile(
        "mma.sync.aligned.m16n8k16.row.col.f32.f16.f16.f32 "
        "{%0,%1,%2,%3}, {%4,%5,%6,%7}, {%8,%9}, {%0,%1,%2,%3};"
        : "+f"(c[0]), "+f"(c[1]), "+f"(c[2]), "+f"(c[3])
        : "r"(a[0]), "r"(a[1]), "r"(a[2]), "r"(a[3]), "r"(b0), "r"(b1));
}

#define CP_ASYNC16(sm, gp) \
    asm volatile("cp.async.cg.shared.global [%0], [%1], 16;" :: "r"(sm), "l"(gp))
#define CP_COMMIT() asm volatile("cp.async.commit_group;" ::: "memory")
#define CP_WAIT_ALL() asm volatile("cp.async.wait_all;" ::: "memory")

// ---------------------------------------------------------------------------
// Kernel 1: L2-normalize 8192 rows -> f16 keys + pre-scaled f16 queries.
// One warp per row, grid 1024 x 256 (R3 config, measured 5.3us).
// ---------------------------------------------------------------------------
__global__ void normalize_kernel(const float* __restrict__ a1,
                                 const float* __restrict__ a2,
                                 const float* __restrict__ a3,
                                 const float* __restrict__ a4) {
    int w = threadIdx.x >> 5, lane = threadIdx.x & 31;
    int row = blockIdx.x * 8 + w;
    const float* src = (row < 2048) ? a1 : (row < 4096) ? a2
                      : (row < 6144) ? a3 : a4;
    int r = row & 2047;
    float4 v = *(const float4*)(src + r * DIMK + lane * 4);
    float ss = v.x * v.x + v.y * v.y + v.z * v.z + v.w * v.w;
#pragma unroll
    for (int off = 16; off; off >>= 1) ss += __shfl_xor_sync(~0u, ss, off);
    float inv = 1.0f / fmaxf(sqrtf(ss), 1e-8f);
    float x = v.x * inv, y = v.y * inv, z = v.z * inv, wv = v.w * inv;
    __half2 b0 = __float22half2_rn(make_float2(x, y));
    __half2 b1 = __float22half2_rn(make_float2(z, wv));
    uint2 st;
    st.x = *(uint32_t*)&b0;
    st.y = *(uint32_t*)&b1;
    ((uint2*)(g_b16 + row * DIMK))[lane] = st;
    if (row < 4096) {
        __half2 s0 = __float22half2_rn(make_float2(SCALEA * x, SCALEA * y));
        __half2 s1 = __float22half2_rn(make_float2(SCALEA * z, SCALEA * wv));
        uint2 sa;
        sa.x = *(uint32_t*)&s0;
        sa.y = *(uint32_t*)&s1;
        ((uint2*)(g_a16 + row * DIMK))[lane] = sa;
    }
}

// ---------------------------------------------------------------------------
// Kernel 2: f16 HMMA GEMM (fp32 acc), R4 structure. CTA tile = 128 rows x
// 512 cols (4 subtiles of 128 cols), K=128 in one shot. 256 threads = 8
// warps (4M x 2N), warp tile 32x64. grid = (32, 16) = 512 CTAs.
// Register row-accumulators across subtiles; last-16-CTA fused finalize.
// ---------------------------------------------------------------------------
#define TSTRIDE 272                 // 128 f16 + 8 pad -> conflict-free ldmatrix
#define SM_A 0
#define SM_B0 (128 * TSTRIDE)       // 34816
#define SM_B1 (2 * 128 * TSTRIDE)   // 69632
#define SMEM_BYTES (3 * 128 * TSTRIDE)  // 104448 -> 2 CTA/SM

__device__ __forceinline__ void issue_tile_load(uint32_t sb, int sm_off,
                                                const __half* src, int grow0,
                                                int tid) {
#pragma unroll
    for (int it = 0; it < 8; it++) {
        int idx = it * 256 + tid;           // 2048 16B vectors
        int r = idx >> 4, g = idx & 15;
        CP_ASYNC16(sb + sm_off + r * TSTRIDE + g * 16,
                   (const char*)(src + (grow0 + r) * DIMK + g * 8));
    }
}

__global__ void __launch_bounds__(256, 2) sim_kernel(float* __restrict__ out) {
    extern __shared__ char smem[];
    uint32_t sb = smem_u32(smem);
    __shared__ int sK, sLast2;
    __shared__ float wred[8];

    int tid = threadIdx.x;
    int lane = tid & 31;
    int w = tid >> 5;
    int wm = w & 3;        // M warp (rows wm*32..+31)
    int wn = w >> 2;       // N warp (cols wn*64..+63)
    int row0 = blockIdx.x * 128;
    int cg = blockIdx.y;                  // cols [cg*512, cg*512+512)

    // ---- prologue: A + B0 ----
    issue_tile_load(sb, SM_A, g_a16, row0, tid);
    issue_tile_load(sb, SM_B0, g_b16, cg * 512, tid);
    CP_COMMIT();

    // ---- ldmatrix lane address bases ----
    int arow = wm * 32 + ((lane >> 3) & 1) * 8 + (lane & 7);
    int akoct = (lane >> 4) * 8;
    uint32_t baseA = sb + SM_A + arow * TSTRIDE + akoct * 2;
    int brow = wn * 64 + ((lane >> 4) & 1) * 8 + (lane & 7);
    int bkoct = ((lane >> 3) & 1) * 8;
    uint32_t baseBoff = brow * TSTRIDE + bkoct * 2;

    int qrow = lane >> 2;          // 0..7
    // ---- per-row diagonal bookkeeping (CTA window = 512 cols) ----
    int half = row0 >> 11;
    int cblk = cg >> 2;                           // which 2048-block
    bool tgt = (cblk == 1 - half);
    int dl0 = (row0 & 2047) - (cg & 3) * 512;

    int nid[4], c_id[4], dsub[4], rloc[4];
    bool fix[4];
#pragma unroll
    for (int mi = 0; mi < 2; mi++)
#pragma unroll
        for (int h = 0; h < 2; h++) {
            int i = mi * 2 + h;
            int row_local = wm * 32 + mi * 16 + qrow + 8 * h;
            rloc[i] = row_local;
            int d = dl0 + row_local;
            dsub[i] = d >> 7;                     // subtile holding the diag
            nid[i] = (d & 63) >> 3;
            c_id[i] = 2 * h + (d & 1);
            fix[i] = (d >= 0) && (d < 512)
                   && (((d >> 6) & 1) == wn)
                   && (((d & 7) >> 1) == (lane & 3));
        }

    float sumReg[4] = {0.f, 0.f, 0.f, 0.f};
    float posReg[4] = {0.f, 0.f, 0.f, 0.f};

    for (int ct = 0; ct < 4; ct++) {
        CP_WAIT_ALL();
        __syncthreads();           // B(ct) visible; all warps done with ct-1

        if (ct < 3) {              // prefetch B(ct+1), overlapped with compute
            issue_tile_load(sb, ((ct + 1) & 1) ? SM_B1 : SM_B0,
                            g_b16, cg * 512 + (ct + 1) * 128, tid);
            CP_COMMIT();
        }

        uint32_t baseB = sb + ((ct & 1) ? SM_B1 : SM_B0) + baseBoff;

        float acc[2][8][4];
#pragma unroll
        for (int mi = 0; mi < 2; mi++)
#pragma unroll
            for (int ni = 0; ni < 8; ni++)
#pragma unroll
                for (int c = 0; c < 4; c++) acc[mi][ni][c] = 0.f;

#pragma unroll
        for (int ks = 0; ks < 8; ks++) {
            uint32_t a[2][4];
            ldsm_x4(a[0], baseA + ks * 32);
            ldsm_x4(a[1], baseA + 16 * TSTRIDE + ks * 32);
            uint32_t b[4][4];
#pragma unroll
            for (int nip = 0; nip < 4; nip++)
                ldsm_x4(b[nip], baseB + nip * 16 * TSTRIDE + ks * 32);
#pragma unroll
            for (int mi = 0; mi < 2; mi++)
#pragma unroll
                for (int nip = 0; nip < 4; nip++) {
                    mma16816(acc[mi][2 * nip + 0], a[mi], b[nip][0], b[nip][1]);
                    mma16816(acc[mi][2 * nip + 1], a[mi], b[nip][2], b[nip][3]);
                }
        }

        // ---- epilogue: ex2-sum (scale pre-folded into A) + diag fixup ----
#pragma unroll
        for (int mi = 0; mi < 2; mi++)
#pragma unroll
            for (int h = 0; h < 2; h++) {
                int i = mi * 2 + h;
                float s = 0.f;
#pragma unroll
                for (int ni = 0; ni < 8; ni++) {
                    s += ex2(acc[mi][ni][2 * h + 0]);
                    s += ex2(acc[mi][ni][2 * h + 1]);
                }
                sumReg[i] += s;
                if (fix[i] && dsub[i] == ct) {
                    float vd = acc[mi][nid[i]][c_id[i]];
                    if (tgt) posReg[i] += vd * LN2F;       // pos = acc*ln2
                    else sumReg[i] -= ex2(vd);             // same term: cancel
                }
            }
    }

    // ---- per-row reduce: 4 col-lanes, then the 2 N warps via SMEM ----
#pragma unroll
    for (int i = 0; i < 4; i++) {
        sumReg[i] += __shfl_xor_sync(~0u, sumReg[i], 1);
        sumReg[i] += __shfl_xor_sync(~0u, sumReg[i], 2);
        posReg[i] += __shfl_xor_sync(~0u, posReg[i], 1);
        posReg[i] += __shfl_xor_sync(~0u, posReg[i], 2);
    }
    float* sS = (float*)(smem + SM_B0);        // B buffers dead after compute
    float* sP = (float*)(smem + SM_B0 + 1024);
    __syncthreads();
    if ((lane & 3) == 0 && wn == 1) {
#pragma unroll
        for (int i = 0; i < 4; i++) {
            sS[rloc[i]] = sumReg[i];
            sP[rloc[i]] = posReg[i];
        }
    }
    __syncthreads();
    if ((lane & 3) == 0 && wn == 0) {
#pragma unroll
        for (int i = 0; i < 4; i++) {
            int row = row0 + rloc[i];
            g_S[row * 16 + cg] = sumReg[i] + sS[rloc[i]];
            g_pos[row * 16 + cg] = posReg[i] + sP[rloc[i]];
        }
    }

    // ---- last-16-CTA finalize (R11 pattern; final wave fully co-resident) --
    __threadfence();
    __syncthreads();
    if (tid == 0) sK = (int)atomicAdd(&g_cnt, 1u);
    __syncthreads();
    int k = sK;
    if (k >= 496) {
        if (k == 511 && tid == 0) atomicExch(&g_flag, 1u);
        if (tid == 0) while (atomicAdd(&g_flag, 0u) == 0u) { }
        __syncthreads();
        __threadfence();
        int row = (k - 496) * 256 + tid;
        const float4* s4 = (const float4*)(g_S + row * 16);
        const float4* p4 = (const float4*)(g_pos + row * 16);
        float S = 0.f, p = 0.f;
#pragma unroll
        for (int q = 0; q < 4; q++) {
            float4 x = s4[q], y = p4[q];
            S += (x.x + x.y) + (x.z + x.w);
            p += (y.x + y.y) + (y.z + y.w);
        }
        float local = logf(S) - p;
#pragma unroll
        for (int off = 16; off; off >>= 1) local += __shfl_xor_sync(~0u, local, off);
        if (lane == 0) wred[tid >> 5] = local;
        __syncthreads();
        if (tid == 0) {
            float t = 0.f;
#pragma unroll
            for (int q = 0; q < 8; q++) t += wred[q];
            g_fin[k - 496] = t;
            __threadfence();
            int k2 = (int)atomicAdd(&g_cnt2, 1u);
            sLast2 = (k2 == 15);
        }
        __syncthreads();
        if (sLast2 && tid == 0) {
            __threadfence();
            float t = 0.f;
#pragma unroll
            for (int q = 0; q < 16; q++) t += g_fin[q];
            out[0] = t / 4096.f;
            g_cnt = 0; g_cnt2 = 0; g_flag = 0;    // reset for graph replay
        }
    }
}

// ---------------------------------------------------------------------------
extern "C" void kernel_launch(void* const* d_in, const int* in_sizes, int n_in,
                              void* d_out, int out_size) {
    const float* a1 = (const float*)d_in[0];
    const float* a2 = (const float*)d_in[1];
    const float* a3 = (const float*)d_in[2];
    const float* a4 = (const float*)d_in[3];

    normalize_kernel<<<1024, 256>>>(a1, a2, a3, a4);

    cudaFuncSetAttribute(sim_kernel, cudaFuncAttributeMaxDynamicSharedMemorySize,
                         SMEM_BYTES);
    dim3 grid(32, 16);
    sim_kernel<<<grid, 256, SMEM_BYTES>>>((float*)d_out);
}

// round 13
// speedup vs baseline: 2.0412x; 1.1779x over previous
#include <cuda_runtime.h>
#include <cuda_fp16.h>
#include <cstdint>

// Problem: N=2048, D=128, k=4, T=0.5.
// rows (queries) = 4096, cols (keys) = 8192.
// sim = norm(z[0:4096]) @ norm(z_all)^T * 2 ; mask non-target diagonals;
// loss = mean(logsumexp - pos). Logits in [-2,2] -> no max subtraction.
//
// f16 operands + f16 accumulators (R7: rel_err 0.0). A = f16(2*log2(e)*zhat)
// -> acc = 2*log2(e)*sim; exp = h2exp2(acc); pos = acc*ln2 (direct global
// store, single writer per row); masked diag subtracts the same exp term.
// NEW: 64x64 warp tiles (8 LDSM : 32 HMMA instead of 6:16) -> 33% fewer LDSM,
// attacking the measured L1/LDSM bottleneck. B streamed in K=64 chunks.

#define DIMK 128
#define SCALEA 2.885390081777927f     // 2 * log2(e)
#define LN2F 0.6931471805599453f

// ---------------- device scratch (no allocations allowed) -------------------
__device__ __half g_a16[4096 * 128];   // scaled normalized queries
__device__ __half g_b16[8192 * 128];   // normalized keys
__device__ float g_S[4096 * 8];        // [row][cg] exp-sum partials
__device__ float g_pos[4096];          // positive logit per row (1 writer)
__device__ float g_fin[16];            // finalize partials
__device__ unsigned int g_cnt, g_cnt2, g_flag;

__device__ __forceinline__ uint32_t smem_u32(const void* p) {
    uint32_t a;
    asm("{ .reg .u64 t; cvta.to.shared.u64 t, %1; cvt.u32.u64 %0, t; }"
        : "=r"(a) : "l"(p));
    return a;
}
__device__ __forceinline__ void ldsm_x4(uint32_t* r, uint32_t addr) {
    asm volatile("ldmatrix.sync.aligned.m8n8.x4.shared.b16 {%0,%1,%2,%3}, [%4];"
                 : "=r"(r[0]), "=r"(r[1]), "=r"(r[2]), "=r"(r[3]) : "r"(addr));
}
__device__ __forceinline__ void mma_h16(uint32_t* c, const uint32_t* a,
                                        uint32_t b0, uint32_t b1) {
    asm volatile(
        "mma.sync.aligned.m16n8k16.row.col.f16.f16.f16.f16 "
        "{%0,%1}, {%2,%3,%4,%5}, {%6,%7}, {%0,%1};"
        : "+r"(c[0]), "+r"(c[1])
        : "r"(a[0]), "r"(a[1]), "r"(a[2]), "r"(a[3]), "r"(b0), "r"(b1));
}

#define CP_ASYNC16(sm, gp) \
    asm volatile("cp.async.cg.shared.global [%0], [%1], 16;" :: "r"(sm), "l"(gp))
#define CP_COMMIT() asm volatile("cp.async.commit_group;" ::: "memory")
#define CP_WAIT_ALL() asm volatile("cp.async.wait_all;" ::: "memory")

// ---------------------------------------------------------------------------
// Kernel 1: L2-normalize 8192 rows -> f16 keys + pre-scaled f16 queries.
// One warp per row, grid 1024 x 256.
// ---------------------------------------------------------------------------
__global__ void normalize_kernel(const float* __restrict__ a1,
                                 const float* __restrict__ a2,
                                 const float* __restrict__ a3,
                                 const float* __restrict__ a4) {
    int w = threadIdx.x >> 5, lane = threadIdx.x & 31;
    int row = blockIdx.x * 8 + w;
    const float* src = (row < 2048) ? a1 : (row < 4096) ? a2
                      : (row < 6144) ? a3 : a4;
    int r = row & 2047;
    float4 v = *(const float4*)(src + r * DIMK + lane * 4);
    float ss = v.x * v.x + v.y * v.y + v.z * v.z + v.w * v.w;
#pragma unroll
    for (int off = 16; off; off >>= 1) ss += __shfl_xor_sync(~0u, ss, off);
    float inv = 1.0f / fmaxf(sqrtf(ss), 1e-8f);
    float x = v.x * inv, y = v.y * inv, z = v.z * inv, wv = v.w * inv;
    __half2 b0 = __float22half2_rn(make_float2(x, y));
    __half2 b1 = __float22half2_rn(make_float2(z, wv));
    uint2 st;
    st.x = *(uint32_t*)&b0;
    st.y = *(uint32_t*)&b1;
    ((uint2*)(g_b16 + row * DIMK))[lane] = st;
    if (row < 4096) {
        __half2 s0 = __float22half2_rn(make_float2(SCALEA * x, SCALEA * y));
        __half2 s1 = __float22half2_rn(make_float2(SCALEA * z, SCALEA * wv));
        uint2 sa;
        sa.x = *(uint32_t*)&s0;
        sa.y = *(uint32_t*)&s1;
        ((uint2*)(g_a16 + row * DIMK))[lane] = sa;
    }
}

// ---------------------------------------------------------------------------
// Kernel 2: f16 HMMA GEMM (f16 acc). CTA tile = 128 rows x 1024 cols.
// 8 warps = 2M x 4N; warp tile 64x64. Steps: 4 subtiles (256 cols) x 2
// K-chunks (64). B chunk (256 x 64k f16 = 32KB) double-buffered via cp.async.
// XOR-swizzled SMEM (R8/R10-validated): 16B chunk c of row r at
// r*RB + ((c ^ (r&7))<<4). A full-K resident (32KB).
// grid = (32 row tiles, 8 col groups) = 256 CTAs, single wave @ 2/SM.
// ---------------------------------------------------------------------------
#define SM_A 0                      // 128 rows x 256B = 32768
#define SM_B0 32768                 // 256 rows x 128B = 32768
#define SM_B1 65536
#define SM_RED 98304                // float sRed[3][128] = 1536
#define SMEM_BYTES (98304 + 1536)

__global__ void __launch_bounds__(256, 2) sim_kernel(float* __restrict__ out) {
    extern __shared__ char smem[];
    uint32_t sb = smem_u32(smem);
    __shared__ int sK, sLast2;
    __shared__ float wred[8];

    int tid = threadIdx.x;
    int lane = tid & 31;
    int w = tid >> 5;
    int wm = w & 1;        // M warp: rows wm*64..+63
    int wn = w >> 1;       // N warp: cols wn*64..+63 within the 256-col subtile
    int row0 = blockIdx.x * 128;
    int cg = blockIdx.y;                  // cols [cg*1024, cg*1024+1024)

    // ---- prologue: A (full K) + B chunk for step 0 ----
#pragma unroll
    for (int it = 0; it < 8; it++) {      // A: 2048 16B vectors
        int idx = it * 256 + tid;
        int rr = idx >> 4, c = idx & 15;
        CP_ASYNC16(sb + SM_A + rr * 256 + (((c ^ (rr & 7)) & 15) << 4),
                   (const char*)(g_a16 + (row0 + rr) * DIMK + c * 8));
    }
#pragma unroll
    for (int it = 0; it < 8; it++) {      // B chunk: 256 rows x 8 chunks
        int idx = it * 256 + tid;
        int rr = idx >> 3, c = idx & 7;
        CP_ASYNC16(sb + SM_B0 + rr * 128 + ((c ^ (rr & 7)) << 4),
                   (const char*)(g_b16 + (cg * 1024 + rr) * DIMK + c * 8));
    }
    CP_COMMIT();

    // ---- lane patterns ----
    int rowpat = ((lane >> 3) & 1) * 8 + (lane & 7);   // A ldsm row-in-16
    int koctA = lane >> 4;                             // 0/1: k octet
    int r7 = lane & 7;                                 // swizzle key (A and B)
    uint32_t baseA = sb + SM_A + (wm * 64 + rowpat) * 256;
    int colpat = ((lane >> 4) & 1) * 8 + (lane & 7);   // B ldsm col-in-16
    int koctB = (lane >> 3) & 1;

    int qrow = lane >> 2;          // 0..7
    // ---- diagonal bookkeeping ----
    int half = row0 >> 11;
    int cblk = cg >> 1;
    bool tgt = (cblk == 1 - half);
    int dl0 = (row0 & 2047) - (cg & 1) * 1024 - (wm * 64 + qrow);
    // dcol for (mi,h): -(dl0') where d = dl0 + wm*64 + mi*16 + qrow + 8h
    // computed inline below.

    float sumReg[8];
#pragma unroll
    for (int i = 0; i < 8; i++) sumReg[i] = 0.f;

    uint32_t acc[4][8][2];   // [mi 16-row group][n8 8-col group][row half]

    for (int s = 0; s < 8; s++) {
        int ct = s >> 1, kc = s & 1;
        CP_WAIT_ALL();
        __syncthreads();               // B(s) ready; all warps done with s-1

        if (s < 7) {                   // prefetch B(s+1) chunk, overlapped
            int ct2 = (s + 1) >> 1, kc2 = (s + 1) & 1;
            uint32_t dst = sb + (((s + 1) & 1) ? SM_B1 : SM_B0);
            const __half* srcB = g_b16 + kc2 * 64;
            int col0n = cg * 1024 + ct2 * 256;
#pragma unroll
            for (int it = 0; it < 8; it++) {
                int idx = it * 256 + tid;
                int rr = idx >> 3, c = idx & 7;
                CP_ASYNC16(dst + rr * 128 + ((c ^ (rr & 7)) << 4),
                           (const char*)(srcB + (col0n + rr) * DIMK + c * 8));
            }
            CP_COMMIT();
        }

        uint32_t bufB = sb + ((s & 1) ? SM_B1 : SM_B0);

        if (kc == 0) {                 // new subtile: zero accumulators
#pragma unroll
            for (int mi = 0; mi < 4; mi++)
#pragma unroll
                for (int n8 = 0; n8 < 8; n8++) {
                    acc[mi][n8][0] = 0u;
                    acc[mi][n8][1] = 0u;
                }
        }

#pragma unroll
        for (int ks = 0; ks < 4; ks++) {
            // A fragments: 4 x ldsm (64 rows), full-K rows (16 chunks)
            int gA = kc * 8 + ks * 2 + koctA;
            uint32_t offA = (uint32_t)(((gA ^ r7) & 15) << 4);
            uint32_t a[4][4];
#pragma unroll
            for (int mi = 0; mi < 4; mi++)
                ldsm_x4(a[mi], baseA + mi * 16 * 256 + offA);
            // B fragments: 4 x ldsm (64 cols), chunk rows (8 chunks)
            int gB = ks * 2 + koctB;
            uint32_t offB = (uint32_t)((gB ^ r7) << 4);
            uint32_t b[4][4];
#pragma unroll
            for (int ns = 0; ns < 4; ns++)
                ldsm_x4(b[ns], bufB + (wn * 64 + ns * 16 + colpat) * 128 + offB);
#pragma unroll
            for (int mi = 0; mi < 4; mi++)
#pragma unroll
                for (int ns = 0; ns < 4; ns++) {
                    mma_h16(acc[mi][2 * ns + 0], a[mi], b[ns][0], b[ns][1]);
                    mma_h16(acc[mi][2 * ns + 1], a[mi], b[ns][2], b[ns][3]);
                }
        }

        if (kc == 1) {                 // subtile complete: exp epilogue
#pragma unroll
            for (int mi = 0; mi < 4; mi++)
#pragma unroll
                for (int h = 0; h < 2; h++) {
                    int i = mi * 2 + h;
                    __half2 e0 = h2exp2(*(__half2*)&acc[mi][0][h]);
                    __half2 e1 = h2exp2(*(__half2*)&acc[mi][1][h]);
                    __half2 e2 = h2exp2(*(__half2*)&acc[mi][2][h]);
                    __half2 e3 = h2exp2(*(__half2*)&acc[mi][3][h]);
                    __half2 e4 = h2exp2(*(__half2*)&acc[mi][4][h]);
                    __half2 e5 = h2exp2(*(__half2*)&acc[mi][5][h]);
                    __half2 e6 = h2exp2(*(__half2*)&acc[mi][6][h]);
                    __half2 e7 = h2exp2(*(__half2*)&acc[mi][7][h]);
                    __half2 t = __hadd2(__hadd2(__hadd2(e0, e1), __hadd2(e2, e3)),
                                        __hadd2(__hadd2(e4, e5), __hadd2(e6, e7)));
                    float2 f = __half22float2(t);
                    sumReg[i] += f.x + f.y;
                    // diag fixup (rare)
                    int rl = wm * 64 + mi * 16 + qrow + 8 * h;
                    int d = dl0 + (wm * 64 + qrow) + mi * 16 + 8 * h;
                    if ((unsigned)d < 1024u && (d >> 8) == ct
                        && ((d >> 6) & 3) == wn
                        && ((d & 7) >> 1) == (lane & 3)) {
                        int n8d = (d & 63) >> 3;
                        __half2 av = *(__half2*)&acc[mi][n8d][h];
                        if (tgt) {
                            float aval = (d & 1) ? __high2float(av)
                                                 : __low2float(av);
                            g_pos[row0 + rl] = aval * LN2F;
                        } else {
                            __half2 ev = h2exp2(av);
                            sumReg[i] -= (d & 1) ? __high2float(ev)
                                                 : __low2float(ev);
                        }
                    }
                }
        }
    }

    // ---- per-row reduce: 4 col-lanes, then the 4 N warps via SMEM ----
#pragma unroll
    for (int i = 0; i < 8; i++) {
        sumReg[i] += __shfl_xor_sync(~0u, sumReg[i], 1);
        sumReg[i] += __shfl_xor_sync(~0u, sumReg[i], 2);
    }
    float* sRed = (float*)(smem + SM_RED);   // [3][128]
    __syncthreads();
    if ((lane & 3) == 0 && wn > 0) {
#pragma unroll
        for (int i = 0; i < 8; i++) {
            int rl = wm * 64 + (i >> 1) * 16 + qrow + 8 * (i & 1);
            sRed[(wn - 1) * 128 + rl] = sumReg[i];
        }
    }
    __syncthreads();
    if ((lane & 3) == 0 && wn == 0) {
#pragma unroll
        for (int i = 0; i < 8; i++) {
            int rl = wm * 64 + (i >> 1) * 16 + qrow + 8 * (i & 1);
            int row = row0 + rl;
            g_S[row * 8 + cg] = sumReg[i] + sRed[rl] + sRed[128 + rl]
                              + sRed[256 + rl];
        }
    }

    // ---- last-16-CTA finalize (R11 pattern; 256 CTAs co-resident wave) ----
    __threadfence();
    __syncthreads();
    if (tid == 0) sK = (int)atomicAdd(&g_cnt, 1u);
    __syncthreads();
    int k = sK;
    if (k >= 240) {
        if (k == 255 && tid == 0) atomicExch(&g_flag, 1u);
        if (tid == 0) while (atomicAdd(&g_flag, 0u) == 0u) { }
        __syncthreads();
        __threadfence();
        int row = (k - 240) * 256 + tid;
        const float4* s4 = (const float4*)(g_S + row * 8);
        float4 x0 = s4[0], x1 = s4[1];
        float S = (x0.x + x0.y) + (x0.z + x0.w) + (x1.x + x1.y) + (x1.z + x1.w);
        float local = logf(S) - g_pos[row];
#pragma unroll
        for (int off = 16; off; off >>= 1) local += __shfl_xor_sync(~0u, local, off);
        if (lane == 0) wred[tid >> 5] = local;
        __syncthreads();
        if (tid == 0) {
            float t = 0.f;
#pragma unroll
            for (int q = 0; q < 8; q++) t += wred[q];
            g_fin[k - 240] = t;
            __threadfence();
            int k2 = (int)atomicAdd(&g_cnt2, 1u);
            sLast2 = (k2 == 15);
        }
        __syncthreads();
        if (sLast2 && tid == 0) {
            __threadfence();
            float t = 0.f;
#pragma unroll
            for (int q = 0; q < 16; q++) t += g_fin[q];
            out[0] = t / 4096.f;
            g_cnt = 0; g_cnt2 = 0; g_flag = 0;    // reset for graph replay
        }
    }
}

// ---------------------------------------------------------------------------
extern "C" void kernel_launch(void* const* d_in, const int* in_sizes, int n_in,
                              void* d_out, int out_size) {
    const float* a1 = (const float*)d_in[0];
    const float* a2 = (const float*)d_in[1];
    const float* a3 = (const float*)d_in[2];
    const float* a4 = (const float*)d_in[3];

    normalize_kernel<<<1024, 256>>>(a1, a2, a3, a4);

    cudaFuncSetAttribute(sim_kernel, cudaFuncAttributeMaxDynamicSharedMemorySize,
                         SMEM_BYTES);
    dim3 grid(32, 8);
    sim_kernel<<<grid, 256, SMEM_BYTES>>>((float*)d_out);
}

// round 15
// speedup vs baseline: 2.2643x; 1.1093x over previous
#include <cuda_runtime.h>
#include <cuda_fp16.h>
#include <cstdint>

// Problem: N=2048, D=128, k=4, T=0.5.
// rows (queries) = 4096, cols (keys) = 8192.
// sim = norm(z[0:4096]) @ norm(z_all)^T * 2 ; mask non-target diagonals;
// loss = mean(logsumexp - pos). Logits in [-2,2] -> no max subtraction.
//
// R13 winning structure (43.5us): f16 operands + f16 accumulators,
// A = f16(2*log2(e)*zhat) -> acc = 2*log2(e)*sim; exp = h2exp2(acc);
// pos = acc*ln2; masked diag subtracts the same exp term. 64x64 warp tiles.
// R15: XOR-folded swizzle addressing done SAFELY — the dynamic SMEM base is
// explicitly 256-aligned (R14's NaN was base-misalignment corrupting the
// folded addresses). Plus hoisted ct-invariant diag bookkeeping.

#define DIMK 128
#define SCALEA 2.885390081777927f     // 2 * log2(e)
#define LN2F 0.6931471805599453f

// ---------------- device scratch (no allocations allowed) -------------------
__device__ __half g_a16[4096 * 128];   // scaled normalized queries
__device__ __half g_b16[8192 * 128];   // normalized keys
__device__ float g_S[4096 * 8];        // [row][cg] exp-sum partials
__device__ float g_pos[4096];          // positive logit per row (1 writer)
__device__ float g_fin[16];            // finalize partials
__device__ unsigned int g_cnt, g_cnt2, g_flag;

__device__ __forceinline__ uint32_t smem_u32(const void* p) {
    uint32_t a;
    asm("{ .reg .u64 t; cvta.to.shared.u64 t, %1; cvt.u32.u64 %0, t; }"
        : "=r"(a) : "l"(p));
    return a;
}
__device__ __forceinline__ void ldsm_x4(uint32_t* r, uint32_t addr) {
    asm volatile("ldmatrix.sync.aligned.m8n8.x4.shared.b16 {%0,%1,%2,%3}, [%4];"
                 : "=r"(r[0]), "=r"(r[1]), "=r"(r[2]), "=r"(r[3]) : "r"(addr));
}
__device__ __forceinline__ void mma_h16(uint32_t* c, const uint32_t* a,
                                        uint32_t b0, uint32_t b1) {
    asm volatile(
        "mma.sync.aligned.m16n8k16.row.col.f16.f16.f16.f16 "
        "{%0,%1}, {%2,%3,%4,%5}, {%6,%7}, {%0,%1};"
        : "+r"(c[0]), "+r"(c[1])
        : "r"(a[0]), "r"(a[1]), "r"(a[2]), "r"(a[3]), "r"(b0), "r"(b1));
}

#define CP_ASYNC16(sm, gp) \
    asm volatile("cp.async.cg.shared.global [%0], [%1], 16;" :: "r"(sm), "l"(gp))
#define CP_COMMIT() asm volatile("cp.async.commit_group;" ::: "memory")
#define CP_WAIT_ALL() asm volatile("cp.async.wait_all;" ::: "memory")

// ---------------------------------------------------------------------------
// Kernel 1: L2-normalize 8192 rows -> f16 keys + pre-scaled f16 queries.
// ---------------------------------------------------------------------------
__global__ void normalize_kernel(const float* __restrict__ a1,
                                 const float* __restrict__ a2,
                                 const float* __restrict__ a3,
                                 const float* __restrict__ a4) {
    int w = threadIdx.x >> 5, lane = threadIdx.x & 31;
    int row = blockIdx.x * 8 + w;
    const float* src = (row < 2048) ? a1 : (row < 4096) ? a2
                      : (row < 6144) ? a3 : a4;
    int r = row & 2047;
    float4 v = *(const float4*)(src + r * DIMK + lane * 4);
    float ss = v.x * v.x + v.y * v.y + v.z * v.z + v.w * v.w;
#pragma unroll
    for (int off = 16; off; off >>= 1) ss += __shfl_xor_sync(~0u, ss, off);
    float inv = 1.0f / fmaxf(sqrtf(ss), 1e-8f);
    float x = v.x * inv, y = v.y * inv, z = v.z * inv, wv = v.w * inv;
    __half2 b0 = __float22half2_rn(make_float2(x, y));
    __half2 b1 = __float22half2_rn(make_float2(z, wv));
    uint2 st;
    st.x = *(uint32_t*)&b0;
    st.y = *(uint32_t*)&b1;
    ((uint2*)(g_b16 + row * DIMK))[lane] = st;
    if (row < 4096) {
        __half2 s0 = __float22half2_rn(make_float2(SCALEA * x, SCALEA * y));
        __half2 s1 = __float22half2_rn(make_float2(SCALEA * z, SCALEA * wv));
        uint2 sa;
        sa.x = *(uint32_t*)&s0;
        sa.y = *(uint32_t*)&s1;
        ((uint2*)(g_a16 + row * DIMK))[lane] = sa;
    }
}

// ---------------------------------------------------------------------------
// Kernel 2: f16 HMMA GEMM (f16 acc). CTA tile = 128 rows x 1024 cols.
// 8 warps = 2M x 4N; warp tile 64x64. Steps: 4 subtiles (256 cols) x 2
// K-chunks (64). B chunk 32KB double-buffered via cp.async.
// XOR swizzle: 16B chunk c of row r at r*RB + ((c ^ (r&7))<<4).
// Addressing folded into the (256-ALIGNED) base: per-LDSM = 1 XOR w/ const.
// grid = (32 row tiles, 8 col groups) = 256 CTAs, single wave @ 2/SM.
// ---------------------------------------------------------------------------
#define SM_A 0                      // 128 rows x 256B = 32768
#define SM_B0 32768                 // 256 rows x 128B = 32768
#define SM_B1 65536
#define SM_RED 98304                // float sRed[3][128] = 1536
#define SMEM_BYTES (98304 + 1536 + 256)   // +256 alignment slack

__global__ void __launch_bounds__(256, 2) sim_kernel(float* __restrict__ out) {
    extern __shared__ char smem[];
    uint32_t sbraw = smem_u32(smem);
    uint32_t sb = (sbraw + 255u) & ~255u;     // 256-aligned: XOR-fold is valid
    __shared__ int sK, sLast2;
    __shared__ float wred[8];

    int tid = threadIdx.x;
    int lane = tid & 31;
    int w = tid >> 5;
    int wm = w & 1;        // M warp: rows wm*64..+63
    int wn = w >> 1;       // N warp: cols wn*64..+63 within the 256-col subtile
    int row0 = blockIdx.x * 128;
    int cg = blockIdx.y;                  // cols [cg*1024, cg*1024+1024)

    // ---- prologue: A (full K) + B chunk for step 0 ----
#pragma unroll
    for (int it = 0; it < 8; it++) {      // A: 2048 16B vectors
        int idx = it * 256 + tid;
        int rr = idx >> 4, c = idx & 15;
        CP_ASYNC16(sb + SM_A + rr * 256 + (((c ^ (rr & 7)) & 15) << 4),
                   (const char*)(g_a16 + (row0 + rr) * DIMK + c * 8));
    }
#pragma unroll
    for (int it = 0; it < 8; it++) {      // B chunk: 256 rows x 8 chunks
        int idx = it * 256 + tid;
        int rr = idx >> 3, c = idx & 7;
        CP_ASYNC16(sb + SM_B0 + rr * 128 + ((c ^ (rr & 7)) << 4),
                   (const char*)(g_b16 + (cg * 1024 + rr) * DIMK + c * 8));
    }
    CP_COMMIT();

    // ---- lane patterns with XOR-folded swizzle (base is 256-aligned) ----
    int rowpat = ((lane >> 3) & 1) * 8 + (lane & 7);   // A ldsm row-in-16
    int koctA = lane >> 4;                             // 0/1: k octet
    int r7 = lane & 7;                                 // swizzle key
    // A: addr(mi, kc, ks) = (baseAx0 ^ (kc<<7) + mi*4096) ^ (ks<<5)
    uint32_t baseAx0 = (sb + SM_A + (wm * 64 + rowpat) * 256)
                     ^ (uint32_t)(r7 << 4) ^ (uint32_t)(koctA << 4);
    int colpat = ((lane >> 4) & 1) * 8 + (lane & 7);   // B ldsm col-in-16
    int koctB = (lane >> 3) & 1;
    // B: addr(ns, ks) = (bufB + baseBoffx + ns*2048) ^ (ks<<5)
    uint32_t baseBoffx = (uint32_t)((wn * 64 + colpat) * 128)
                       ^ (uint32_t)(r7 << 4) ^ (uint32_t)(koctB << 4);

    int qrow = lane >> 2;          // 0..7
    // ---- diag bookkeeping: hoisted, ct-invariant ----
    int half = row0 >> 11;
    int cblk = cg >> 1;
    bool tgt = (cblk == 1 - half);
    bool own[8];
    int dsub[8], n8d[8], dlo[8], rlA[8];
#pragma unroll
    for (int mi = 0; mi < 4; mi++)
#pragma unroll
        for (int h = 0; h < 2; h++) {
            int i = mi * 2 + h;
            int rl = wm * 64 + mi * 16 + qrow + 8 * h;
            rlA[i] = rl;
            int d = (row0 & 2047) + rl - (cg & 1) * 1024;
            own[i] = ((unsigned)d < 1024u) && (((d >> 6) & 3) == wn)
                   && (((d & 7) >> 1) == (lane & 3));
            dsub[i] = d >> 8;
            n8d[i] = (d & 63) >> 3;
            dlo[i] = d & 1;
        }

    float sumReg[8];
#pragma unroll
    for (int i = 0; i < 8; i++) sumReg[i] = 0.f;

    uint32_t acc[4][8][2];   // [mi 16-row group][n8 8-col group][row half]

    for (int s = 0; s < 8; s++) {
        int ct = s >> 1, kc = s & 1;
        CP_WAIT_ALL();
        __syncthreads();               // B(s) ready; all warps done with s-1

        if (s < 7) {                   // prefetch B(s+1) chunk, overlapped
            int ct2 = (s + 1) >> 1, kc2 = (s + 1) & 1;
            uint32_t dst = sb + (((s + 1) & 1) ? SM_B1 : SM_B0);
            const __half* srcB = g_b16 + kc2 * 64;
            int col0n = cg * 1024 + ct2 * 256;
#pragma unroll
            for (int it = 0; it < 8; it++) {
                int idx = it * 256 + tid;
                int rr = idx >> 3, c = idx & 7;
                CP_ASYNC16(dst + rr * 128 + ((c ^ (rr & 7)) << 4),
                           (const char*)(srcB + (col0n + rr) * DIMK + c * 8));
            }
            CP_COMMIT();
        }

        uint32_t baseAxk = baseAx0 ^ (uint32_t)(kc << 7);
        uint32_t baseBx = (sb + ((s & 1) ? SM_B1 : SM_B0)) + baseBoffx;

        if (kc == 0) {                 // new subtile: zero accumulators
#pragma unroll
            for (int mi = 0; mi < 4; mi++)
#pragma unroll
                for (int n8 = 0; n8 < 8; n8++) {
                    acc[mi][n8][0] = 0u;
                    acc[mi][n8][1] = 0u;
                }
        }

#pragma unroll
        for (int ks = 0; ks < 4; ks++) {
            uint32_t a[4][4];
#pragma unroll
            for (int mi = 0; mi < 4; mi++)
                ldsm_x4(a[mi], (baseAxk + (uint32_t)(mi * 4096))
                               ^ (uint32_t)(ks << 5));
            uint32_t b[4][4];
#pragma unroll
            for (int ns = 0; ns < 4; ns++)
                ldsm_x4(b[ns], (baseBx + (uint32_t)(ns * 2048))
                               ^ (uint32_t)(ks << 5));
#pragma unroll
            for (int mi = 0; mi < 4; mi++)
#pragma unroll
                for (int ns = 0; ns < 4; ns++) {
                    mma_h16(acc[mi][2 * ns + 0], a[mi], b[ns][0], b[ns][1]);
                    mma_h16(acc[mi][2 * ns + 1], a[mi], b[ns][2], b[ns][3]);
                }
        }

        if (kc == 1) {                 // subtile complete: exp epilogue
#pragma unroll
            for (int mi = 0; mi < 4; mi++)
#pragma unroll
                for (int h = 0; h < 2; h++) {
                    int i = mi * 2 + h;
                    __half2 e0 = h2exp2(*(__half2*)&acc[mi][0][h]);
                    __half2 e1 = h2exp2(*(__half2*)&acc[mi][1][h]);
                    __half2 e2 = h2exp2(*(__half2*)&acc[mi][2][h]);
                    __half2 e3 = h2exp2(*(__half2*)&acc[mi][3][h]);
                    __half2 e4 = h2exp2(*(__half2*)&acc[mi][4][h]);
                    __half2 e5 = h2exp2(*(__half2*)&acc[mi][5][h]);
                    __half2 e6 = h2exp2(*(__half2*)&acc[mi][6][h]);
                    __half2 e7 = h2exp2(*(__half2*)&acc[mi][7][h]);
                    __half2 t = __hadd2(__hadd2(__hadd2(e0, e1), __hadd2(e2, e3)),
                                        __hadd2(__hadd2(e4, e5), __hadd2(e6, e7)));
                    float2 f = __half22float2(t);
                    sumReg[i] += f.x + f.y;
                    if (own[i] && dsub[i] == ct) {      // rare diag fixup
                        __half2 av = *(__half2*)&acc[mi][n8d[i]][h];
                        if (tgt) {
                            float aval = dlo[i] ? __high2float(av)
                                                : __low2float(av);
                            g_pos[row0 + rlA[i]] = aval * LN2F;
                        } else {
                            __half2 ev = h2exp2(av);
                            sumReg[i] -= dlo[i] ? __high2float(ev)
                                                : __low2float(ev);
                        }
                    }
                }
        }
    }

    // ---- per-row reduce: 4 col-lanes, then the 4 N warps via SMEM ----
#pragma unroll
    for (int i = 0; i < 8; i++) {
        sumReg[i] += __shfl_xor_sync(~0u, sumReg[i], 1);
        sumReg[i] += __shfl_xor_sync(~0u, sumReg[i], 2);
    }
    float* sRed = (float*)(uintptr_t)(0);   // placeholder (see below)
    (void)sRed;
    __syncthreads();
    if ((lane & 3) == 0 && wn > 0) {
#pragma unroll
        for (int i = 0; i < 8; i++) {
            uint32_t addr = sb + SM_RED + ((wn - 1) * 128 + rlA[i]) * 4;
            asm volatile("st.shared.f32 [%0], %1;" :: "r"(addr), "f"(sumReg[i]));
        }
    }
    __syncthreads();
    if ((lane & 3) == 0 && wn == 0) {
#pragma unroll
        for (int i = 0; i < 8; i++) {
            int rl = rlA[i];
            float v0, v1, v2;
            uint32_t a0 = sb + SM_RED + rl * 4;
            asm volatile("ld.shared.f32 %0, [%1];" : "=f"(v0) : "r"(a0));
            asm volatile("ld.shared.f32 %0, [%1];" : "=f"(v1) : "r"(a0 + 512));
            asm volatile("ld.shared.f32 %0, [%1];" : "=f"(v2) : "r"(a0 + 1024));
            int row = row0 + rl;
            g_S[row * 8 + cg] = sumReg[i] + v0 + v1 + v2;
        }
    }

    // ---- last-16-CTA finalize (R11 pattern; 256 CTAs co-resident wave) ----
    __threadfence();
    __syncthreads();
    if (tid == 0) sK = (int)atomicAdd(&g_cnt, 1u);
    __syncthreads();
    int k = sK;
    if (k >= 240) {
        if (k == 255 && tid == 0) atomicExch(&g_flag, 1u);
        if (tid == 0) while (atomicAdd(&g_flag, 0u) == 0u) { }
        __syncthreads();
        __threadfence();
        int row = (k - 240) * 256 + tid;
        const float4* s4 = (const float4*)(g_S + row * 8);
        float4 x0 = s4[0], x1 = s4[1];
        float S = (x0.x + x0.y) + (x0.z + x0.w) + (x1.x + x1.y) + (x1.z + x1.w);
        float local = logf(S) - g_pos[row];
#pragma unroll
        for (int off = 16; off; off >>= 1) local += __shfl_xor_sync(~0u, local, off);
        if (lane == 0) wred[tid >> 5] = local;
        __syncthreads();
        if (tid == 0) {
            float t = 0.f;
#pragma unroll
            for (int q = 0; q < 8; q++) t += wred[q];
            g_fin[k - 240] = t;
            __threadfence();
            int k2 = (int)atomicAdd(&g_cnt2, 1u);
            sLast2 = (k2 == 15);
        }
        __syncthreads();
        if (sLast2 && tid == 0) {
            __threadfence();
            float t = 0.f;
#pragma unroll
            for (int q = 0; q < 16; q++) t += g_fin[q];
            out[0] = t / 4096.f;
            g_cnt = 0; g_cnt2 = 0; g_flag = 0;    // reset for graph replay
        }
    }
}

// ---------------------------------------------------------------------------
extern "C" void kernel_launch(void* const* d_in, const int* in_sizes, int n_in,
                              void* d_out, int out_size) {
    const float* a1 = (const float*)d_in[0];
    const float* a2 = (const float*)d_in[1];
    const float* a3 = (const float*)d_in[2];
    const float* a4 = (const float*)d_in[3];

    normalize_kernel<<<1024, 256>>>(a1, a2, a3, a4);

    cudaFuncSetAttribute(sim_kernel, cudaFuncAttributeMaxDynamicSharedMemorySize,
                         SMEM_BYTES);
    dim3 grid(32, 8);
    sim_kernel<<<grid, 256, SMEM_BYTES>>>((float*)d_out);
}

// round 16
// speedup vs baseline: 2.3626x; 1.0434x over previous
#include <cuda_runtime.h>
#include <cuda_fp16.h>
#include <cstdint>

// Problem: N=2048, D=128, k=4, T=0.5.
// rows (queries) = 4096, cols (keys) = 8192.
// sim = norm(z[0:4096]) @ norm(z_all)^T * 2 ; mask non-target diagonals;
// loss = mean(logsumexp - pos). Logits in [-2,2] -> no max subtraction.
//
// R15 winning structure (39.2us): f16 operands + f16 accumulators,
// A = f16(2*log2(e)*zhat) -> acc = 2*log2(e)*sim; exp = h2exp2(acc);
// pos = acc*ln2; masked diag subtracts the same exp term. 64x64 warp tiles,
// 256-aligned XOR-folded swizzle addressing (1 LOP per LDSM).
// R16: strength-reduced cp.async addressing (affine: per-thread base +
// it*stride immediates), fully unrolled main loop -> cut residual ALU.

#define DIMK 128
#define SCALEA 2.885390081777927f     // 2 * log2(e)
#define LN2F 0.6931471805599453f

// ---------------- device scratch (no allocations allowed) -------------------
__device__ __half g_a16[4096 * 128];   // scaled normalized queries
__device__ __half g_b16[8192 * 128];   // normalized keys
__device__ float g_S[4096 * 8];        // [row][cg] exp-sum partials
__device__ float g_pos[4096];          // positive logit per row (1 writer)
__device__ float g_fin[16];            // finalize partials
__device__ unsigned int g_cnt, g_cnt2, g_flag;

__device__ __forceinline__ uint32_t smem_u32(const void* p) {
    uint32_t a;
    asm("{ .reg .u64 t; cvta.to.shared.u64 t, %1; cvt.u32.u64 %0, t; }"
        : "=r"(a) : "l"(p));
    return a;
}
__device__ __forceinline__ void ldsm_x4(uint32_t* r, uint32_t addr) {
    asm volatile("ldmatrix.sync.aligned.m8n8.x4.shared.b16 {%0,%1,%2,%3}, [%4];"
                 : "=r"(r[0]), "=r"(r[1]), "=r"(r[2]), "=r"(r[3]) : "r"(addr));
}
__device__ __forceinline__ void mma_h16(uint32_t* c, const uint32_t* a,
                                        uint32_t b0, uint32_t b1) {
    asm volatile(
        "mma.sync.aligned.m16n8k16.row.col.f16.f16.f16.f16 "
        "{%0,%1}, {%2,%3,%4,%5}, {%6,%7}, {%0,%1};"
        : "+r"(c[0]), "+r"(c[1])
        : "r"(a[0]), "r"(a[1]), "r"(a[2]), "r"(a[3]), "r"(b0), "r"(b1));
}

#define CP_ASYNC16(sm, gp) \
    asm volatile("cp.async.cg.shared.global [%0], [%1], 16;" :: "r"(sm), "l"(gp))
#define CP_COMMIT() asm volatile("cp.async.commit_group;" ::: "memory")
#define CP_WAIT_ALL() asm volatile("cp.async.wait_all;" ::: "memory")

// ---------------------------------------------------------------------------
// Kernel 1: L2-normalize 8192 rows -> f16 keys + pre-scaled f16 queries.
// ---------------------------------------------------------------------------
__global__ void normalize_kernel(const float* __restrict__ a1,
                                 const float* __restrict__ a2,
                                 const float* __restrict__ a3,
                                 const float* __restrict__ a4) {
    int w = threadIdx.x >> 5, lane = threadIdx.x & 31;
    int row = blockIdx.x * 8 + w;
    const float* src = (row < 2048) ? a1 : (row < 4096) ? a2
                      : (row < 6144) ? a3 : a4;
    int r = row & 2047;
    float4 v = *(const float4*)(src + r * DIMK + lane * 4);
    float ss = v.x * v.x + v.y * v.y + v.z * v.z + v.w * v.w;
#pragma unroll
    for (int off = 16; off; off >>= 1) ss += __shfl_xor_sync(~0u, ss, off);
    float inv = 1.0f / fmaxf(sqrtf(ss), 1e-8f);
    float x = v.x * inv, y = v.y * inv, z = v.z * inv, wv = v.w * inv;
    __half2 b0 = __float22half2_rn(make_float2(x, y));
    __half2 b1 = __float22half2_rn(make_float2(z, wv));
    uint2 st;
    st.x = *(uint32_t*)&b0;
    st.y = *(uint32_t*)&b1;
    ((uint2*)(g_b16 + row * DIMK))[lane] = st;
    if (row < 4096) {
        __half2 s0 = __float22half2_rn(make_float2(SCALEA * x, SCALEA * y));
        __half2 s1 = __float22half2_rn(make_float2(SCALEA * z, SCALEA * wv));
        uint2 sa;
        sa.x = *(uint32_t*)&s0;
        sa.y = *(uint32_t*)&s1;
        ((uint2*)(g_a16 + row * DIMK))[lane] = sa;
    }
}

// ---------------------------------------------------------------------------
// Kernel 2: f16 HMMA GEMM (f16 acc). CTA tile = 128 rows x 1024 cols.
// 8 warps = 2M x 4N; warp tile 64x64. Steps: 4 subtiles (256 cols) x 2
// K-chunks (64). B chunk 32KB double-buffered via cp.async.
// Strength-reduced affine cp.async addressing; XOR-folded LDSM swizzle
// (256-aligned base). grid = (32, 8) = 256 CTAs, single wave @ 2/SM.
// ---------------------------------------------------------------------------
#define SM_A 0                      // 128 rows x 256B = 32768
#define SM_B0 32768                 // 256 rows x 128B = 32768
#define SM_B1 65536
#define SM_RED 98304                // float sRed[3][128] = 1536
#define SMEM_BYTES (98304 + 1536 + 256)   // +256 alignment slack

__global__ void __launch_bounds__(256, 2) sim_kernel(float* __restrict__ out) {
    extern __shared__ char smem[];
    uint32_t sbraw = smem_u32(smem);
    uint32_t sb = (sbraw + 255u) & ~255u;     // 256-aligned: XOR-fold is valid
    __shared__ int sK, sLast2;
    __shared__ float wred[8];

    int tid = threadIdx.x;
    int lane = tid & 31;
    int w = tid >> 5;
    int wm = w & 1;        // M warp: rows wm*64..+63
    int wn = w >> 1;       // N warp: cols wn*64..+63 within the 256-col subtile
    int row0 = blockIdx.x * 128;
    int cg = blockIdx.y;                  // cols [cg*1024, cg*1024+1024)

    // ---- strength-reduced load addressing (affine in iteration index) ----
    // A tile: idx = it*256+tid -> rr = it*16 + (tid>>4), c = tid&15 (const),
    //         rr&7 = (tid>>4)&7 (const). dst & src strides = 4096 B.
    uint32_t aDst = sb + SM_A + ((tid >> 4) * 256)
                  + ((((tid & 15) ^ ((tid >> 4) & 7)) & 15) << 4);
    const char* aSrc = (const char*)g_a16 + (size_t)row0 * 256
                     + (tid >> 4) * 256 + (tid & 15) * 16;
    // B chunk: idx = it*256+tid -> rr = it*32 + (tid>>3), c = tid&7 (const),
    //          rr&7 = (tid>>3)&7 (const). dst stride 4096 B, src stride 8192 B.
    uint32_t bDstOff = ((tid >> 3) * 128)
                     + (((tid & 7) ^ ((tid >> 3) & 7)) << 4);
    const char* bSrc00 = (const char*)g_b16 + (size_t)cg * 262144   // cg*1024*256
                       + (tid >> 3) * 256 + (tid & 7) * 16;

    // ---- prologue: A (full K) + B chunk for step 0 ----
#pragma unroll
    for (int it = 0; it < 8; it++)
        CP_ASYNC16(aDst + it * 4096, aSrc + it * 4096);
#pragma unroll
    for (int it = 0; it < 8; it++)
        CP_ASYNC16(sb + SM_B0 + bDstOff + it * 4096, bSrc00 + it * 8192);
    CP_COMMIT();

    // ---- lane patterns with XOR-folded swizzle (base is 256-aligned) ----
    int rowpat = ((lane >> 3) & 1) * 8 + (lane & 7);   // A ldsm row-in-16
    int koctA = lane >> 4;                             // 0/1: k octet
    int r7 = lane & 7;                                 // swizzle key
    uint32_t baseAx0 = (sb + SM_A + (wm * 64 + rowpat) * 256)
                     ^ (uint32_t)(r7 << 4) ^ (uint32_t)(koctA << 4);
    int colpat = ((lane >> 4) & 1) * 8 + (lane & 7);   // B ldsm col-in-16
    int koctB = (lane >> 3) & 1;
    uint32_t baseBoffx = (uint32_t)((wn * 64 + colpat) * 128)
                       ^ (uint32_t)(r7 << 4) ^ (uint32_t)(koctB << 4);

    int qrow = lane >> 2;          // 0..7
    // ---- diag bookkeeping: hoisted, ct-invariant ----
    int half = row0 >> 11;
    int cblk = cg >> 1;
    bool tgt = (cblk == 1 - half);
    bool own[8];
    int dsub[8], n8d[8], dlo[8], rlA[8];
#pragma unroll
    for (int mi = 0; mi < 4; mi++)
#pragma unroll
        for (int h = 0; h < 2; h++) {
            int i = mi * 2 + h;
            int rl = wm * 64 + mi * 16 + qrow + 8 * h;
            rlA[i] = rl;
            int d = (row0 & 2047) + rl - (cg & 1) * 1024;
            own[i] = ((unsigned)d < 1024u) && (((d >> 6) & 3) == wn)
                   && (((d & 7) >> 1) == (lane & 3));
            dsub[i] = d >> 8;
            n8d[i] = (d & 63) >> 3;
            dlo[i] = d & 1;
        }

    float sumReg[8];
#pragma unroll
    for (int i = 0; i < 8; i++) sumReg[i] = 0.f;

    uint32_t acc[4][8][2];   // [mi 16-row group][n8 8-col group][row half]

#pragma unroll
    for (int s = 0; s < 8; s++) {
        const int ct = s >> 1, kc = s & 1;
        CP_WAIT_ALL();
        __syncthreads();               // B(s) ready; all warps done with s-1

        if (s < 7) {                   // prefetch B(s+1) chunk, overlapped
            const int ct2 = (s + 1) >> 1, kc2 = (s + 1) & 1;
            uint32_t dst = sb + (((s + 1) & 1) ? SM_B1 : SM_B0) + bDstOff;
            const char* srcp = bSrc00 + ct2 * 65536 + kc2 * 128;
#pragma unroll
            for (int it = 0; it < 8; it++)
                CP_ASYNC16(dst + it * 4096, srcp + it * 8192);
            CP_COMMIT();
        }

        uint32_t baseAxk = baseAx0 ^ (uint32_t)(kc << 7);
        uint32_t baseBx = (sb + ((s & 1) ? SM_B1 : SM_B0)) + baseBoffx;

        if (kc == 0) {                 // new subtile: zero accumulators
#pragma unroll
            for (int mi = 0; mi < 4; mi++)
#pragma unroll
                for (int n8 = 0; n8 < 8; n8++) {
                    acc[mi][n8][0] = 0u;
                    acc[mi][n8][1] = 0u;
                }
        }

#pragma unroll
        for (int ks = 0; ks < 4; ks++) {
            uint32_t a[4][4];
#pragma unroll
            for (int mi = 0; mi < 4; mi++)
                ldsm_x4(a[mi], (baseAxk + (uint32_t)(mi * 4096))
                               ^ (uint32_t)(ks << 5));
            uint32_t b[4][4];
#pragma unroll
            for (int ns = 0; ns < 4; ns++)
                ldsm_x4(b[ns], (baseBx + (uint32_t)(ns * 2048))
                               ^ (uint32_t)(ks << 5));
#pragma unroll
            for (int mi = 0; mi < 4; mi++)
#pragma unroll
                for (int ns = 0; ns < 4; ns++) {
                    mma_h16(acc[mi][2 * ns + 0], a[mi], b[ns][0], b[ns][1]);
                    mma_h16(acc[mi][2 * ns + 1], a[mi], b[ns][2], b[ns][3]);
                }
        }

        if (kc == 1) {                 // subtile complete: exp epilogue
#pragma unroll
            for (int mi = 0; mi < 4; mi++)
#pragma unroll
                for (int h = 0; h < 2; h++) {
                    int i = mi * 2 + h;
                    __half2 e0 = h2exp2(*(__half2*)&acc[mi][0][h]);
                    __half2 e1 = h2exp2(*(__half2*)&acc[mi][1][h]);
                    __half2 e2 = h2exp2(*(__half2*)&acc[mi][2][h]);
                    __half2 e3 = h2exp2(*(__half2*)&acc[mi][3][h]);
                    __half2 e4 = h2exp2(*(__half2*)&acc[mi][4][h]);
                    __half2 e5 = h2exp2(*(__half2*)&acc[mi][5][h]);
                    __half2 e6 = h2exp2(*(__half2*)&acc[mi][6][h]);
                    __half2 e7 = h2exp2(*(__half2*)&acc[mi][7][h]);
                    __half2 t = __hadd2(__hadd2(__hadd2(e0, e1), __hadd2(e2, e3)),
                                        __hadd2(__hadd2(e4, e5), __hadd2(e6, e7)));
                    float2 f = __half22float2(t);
                    sumReg[i] += f.x + f.y;
                    if (own[i] && dsub[i] == ct) {      // rare diag fixup
                        __half2 av = *(__half2*)&acc[mi][n8d[i]][h];
                        if (tgt) {
                            float aval = dlo[i] ? __high2float(av)
                                                : __low2float(av);
                            g_pos[row0 + rlA[i]] = aval * LN2F;
                        } else {
                            __half2 ev = h2exp2(av);
                            sumReg[i] -= dlo[i] ? __high2float(ev)
                                                : __low2float(ev);
                        }
                    }
                }
        }
    }

    // ---- per-row reduce: 4 col-lanes, then the 4 N warps via SMEM ----
#pragma unroll
    for (int i = 0; i < 8; i++) {
        sumReg[i] += __shfl_xor_sync(~0u, sumReg[i], 1);
        sumReg[i] += __shfl_xor_sync(~0u, sumReg[i], 2);
    }
    __syncthreads();
    if ((lane & 3) == 0 && wn > 0) {
#pragma unroll
        for (int i = 0; i < 8; i++) {
            uint32_t addr = sb + SM_RED + ((wn - 1) * 128 + rlA[i]) * 4;
            asm volatile("st.shared.f32 [%0], %1;" :: "r"(addr), "f"(sumReg[i]));
        }
    }
    __syncthreads();
    if ((lane & 3) == 0 && wn == 0) {
#pragma unroll
        for (int i = 0; i < 8; i++) {
            int rl = rlA[i];
            float v0, v1, v2;
            uint32_t a0 = sb + SM_RED + rl * 4;
            asm volatile("ld.shared.f32 %0, [%1];" : "=f"(v0) : "r"(a0));
            asm volatile("ld.shared.f32 %0, [%1];" : "=f"(v1) : "r"(a0 + 512));
            asm volatile("ld.shared.f32 %0, [%1];" : "=f"(v2) : "r"(a0 + 1024));
            int row = row0 + rl;
            g_S[row * 8 + cg] = sumReg[i] + v0 + v1 + v2;
        }
    }

    // ---- last-16-CTA finalize (256 CTAs co-resident wave) ----
    __threadfence();
    __syncthreads();
    if (tid == 0) sK = (int)atomicAdd(&g_cnt, 1u);
    __syncthreads();
    int k = sK;
    if (k >= 240) {
        if (k == 255 && tid == 0) atomicExch(&g_flag, 1u);
        if (tid == 0) while (atomicAdd(&g_flag, 0u) == 0u) { }
        __syncthreads();
        __threadfence();
        int row = (k - 240) * 256 + tid;
        const float4* s4 = (const float4*)(g_S + row * 8);
        float4 x0 = s4[0], x1 = s4[1];
        float S = (x0.x + x0.y) + (x0.z + x0.w) + (x1.x + x1.y) + (x1.z + x1.w);
        float local = logf(S) - g_pos[row];
#pragma unroll
        for (int off = 16; off; off >>= 1) local += __shfl_xor_sync(~0u, local, off);
        if (lane == 0) wred[tid >> 5] = local;
        __syncthreads();
        if (tid == 0) {
            float t = 0.f;
#pragma unroll
            for (int q = 0; q < 8; q++) t += wred[q];
            g_fin[k - 240] = t;
            __threadfence();
            int k2 = (int)atomicAdd(&g_cnt2, 1u);
            sLast2 = (k2 == 15);
        }
        __syncthreads();
        if (sLast2 && tid == 0) {
            __threadfence();
            float t = 0.f;
#pragma unroll
            for (int q = 0; q < 16; q++) t += g_fin[q];
            out[0] = t / 4096.f;
            g_cnt = 0; g_cnt2 = 0; g_flag = 0;    // reset for graph replay
        }
    }
}

// ---------------------------------------------------------------------------
extern "C" void kernel_launch(void* const* d_in, const int* in_sizes, int n_in,
                              void* d_out, int out_size) {
    const float* a1 = (const float*)d_in[0];
    const float* a2 = (const float*)d_in[1];
    const float* a3 = (const float*)d_in[2];
    const float* a4 = (const float*)d_in[3];

    normalize_kernel<<<1024, 256>>>(a1, a2, a3, a4);

    cudaFuncSetAttribute(sim_kernel, cudaFuncAttributeMaxDynamicSharedMemorySize,
                         SMEM_BYTES);
    dim3 grid(32, 8);
    sim_kernel<<<grid, 256, SMEM_BYTES>>>((float*)d_out);
}

// round 17
// speedup vs baseline: 2.4014x; 1.0164x over previous
#include <cuda_runtime.h>
#include <cuda_fp16.h>
#include <cstdint>

// Problem: N=2048, D=128, k=4, T=0.5.
// rows (queries) = 4096, cols (keys) = 8192.
// sim = norm(z[0:4096]) @ norm(z_all)^T * 2 ; mask non-target diagonals;
// loss = mean(logsumexp - pos). Logits in [-2,2] -> no max subtraction.
//
// R16 winning structure (37.6us): f16 operands + f16 accumulators,
// A = f16(2*log2(e)*zhat) -> acc = 2*log2(e)*sim; exp = h2exp2(acc);
// pos = acc*ln2; masked diag subtracts the same exp term. 64x64 warp tiles,
// 256-aligned XOR-folded swizzle, strength-reduced cp.async addressing.
// R17: DEFERRED EPILOGUE — each subtile's exp chain runs inside the next
// subtile's kc0 region (after the barrier, interleaved with LDSM/MMA issue);
// first MMA of each subtile uses a zero C operand instead of pre-zeroed acc,
// keeping the old acc readable until overwrite. Tensor/MUFU/LDS overlap.

#define DIMK 128
#define SCALEA 2.885390081777927f     // 2 * log2(e)
#define LN2F 0.6931471805599453f

// ---------------- device scratch (no allocations allowed) -------------------
__device__ __half g_a16[4096 * 128];   // scaled normalized queries
__device__ __half g_b16[8192 * 128];   // normalized keys
__device__ float g_S[4096 * 8];        // [row][cg] exp-sum partials
__device__ float g_pos[4096];          // positive logit per row (1 writer)
__device__ float g_fin[16];            // finalize partials
__device__ unsigned int g_cnt, g_cnt2, g_flag;

__device__ __forceinline__ uint32_t smem_u32(const void* p) {
    uint32_t a;
    asm("{ .reg .u64 t; cvta.to.shared.u64 t, %1; cvt.u32.u64 %0, t; }"
        : "=r"(a) : "l"(p));
    return a;
}
__device__ __forceinline__ void ldsm_x4(uint32_t* r, uint32_t addr) {
    asm volatile("ldmatrix.sync.aligned.m8n8.x4.shared.b16 {%0,%1,%2,%3}, [%4];"
                 : "=r"(r[0]), "=r"(r[1]), "=r"(r[2]), "=r"(r[3]) : "r"(addr));
}
__device__ __forceinline__ void mma_h16(uint32_t* c, const uint32_t* a,
                                        uint32_t b0, uint32_t b1) {
    asm volatile(
        "mma.sync.aligned.m16n8k16.row.col.f16.f16.f16.f16 "
        "{%0,%1}, {%2,%3,%4,%5}, {%6,%7}, {%0,%1};"
        : "+r"(c[0]), "+r"(c[1])
        : "r"(a[0]), "r"(a[1]), "r"(a[2]), "r"(a[3]), "r"(b0), "r"(b1));
}
// First MMA of a subtile: C = {0,0} (old acc stays readable until this write).
__device__ __forceinline__ void mma_h16_zc(uint32_t* c, const uint32_t* a,
                                           uint32_t b0, uint32_t b1) {
    asm volatile(
        "mma.sync.aligned.m16n8k16.row.col.f16.f16.f16.f16 "
        "{%0,%1}, {%2,%3,%4,%5}, {%6,%7}, {%8,%8};"
        : "=r"(c[0]), "=r"(c[1])
        : "r"(a[0]), "r"(a[1]), "r"(a[2]), "r"(a[3]), "r"(b0), "r"(b1),
          "r"(0u));
}

#define CP_ASYNC16(sm, gp) \
    asm volatile("cp.async.cg.shared.global [%0], [%1], 16;" :: "r"(sm), "l"(gp))
#define CP_COMMIT() asm volatile("cp.async.commit_group;" ::: "memory")
#define CP_WAIT_ALL() asm volatile("cp.async.wait_all;" ::: "memory")

// ---------------------------------------------------------------------------
// Kernel 1: L2-normalize 8192 rows -> f16 keys + pre-scaled f16 queries.
// ---------------------------------------------------------------------------
__global__ void normalize_kernel(const float* __restrict__ a1,
                                 const float* __restrict__ a2,
                                 const float* __restrict__ a3,
                                 const float* __restrict__ a4) {
    int w = threadIdx.x >> 5, lane = threadIdx.x & 31;
    int row = blockIdx.x * 8 + w;
    const float* src = (row < 2048) ? a1 : (row < 4096) ? a2
                      : (row < 6144) ? a3 : a4;
    int r = row & 2047;
    float4 v = *(const float4*)(src + r * DIMK + lane * 4);
    float ss = v.x * v.x + v.y * v.y + v.z * v.z + v.w * v.w;
#pragma unroll
    for (int off = 16; off; off >>= 1) ss += __shfl_xor_sync(~0u, ss, off);
    float inv = 1.0f / fmaxf(sqrtf(ss), 1e-8f);
    float x = v.x * inv, y = v.y * inv, z = v.z * inv, wv = v.w * inv;
    __half2 b0 = __float22half2_rn(make_float2(x, y));
    __half2 b1 = __float22half2_rn(make_float2(z, wv));
    uint2 st;
    st.x = *(uint32_t*)&b0;
    st.y = *(uint32_t*)&b1;
    ((uint2*)(g_b16 + row * DIMK))[lane] = st;
    if (row < 4096) {
        __half2 s0 = __float22half2_rn(make_float2(SCALEA * x, SCALEA * y));
        __half2 s1 = __float22half2_rn(make_float2(SCALEA * z, SCALEA * wv));
        uint2 sa;
        sa.x = *(uint32_t*)&s0;
        sa.y = *(uint32_t*)&s1;
        ((uint2*)(g_a16 + row * DIMK))[lane] = sa;
    }
}

// ---------------------------------------------------------------------------
// Kernel 2: f16 HMMA GEMM (f16 acc). CTA tile = 128 rows x 1024 cols.
// 8 warps = 2M x 4N; warp tile 64x64. Steps: 4 subtiles (256 cols) x 2
// K-chunks (64). B chunk 32KB double-buffered via cp.async.
// Deferred epilogue: subtile p's exp chain runs at step s=2p+2 (kc0 of
// subtile p+1), interleaved with that step's LDSM/MMA; last subtile after
// the loop. grid = (32, 8) = 256 CTAs, single wave @ 2/SM.
// ---------------------------------------------------------------------------
#define SM_A 0                      // 128 rows x 256B = 32768
#define SM_B0 32768                 // 256 rows x 128B = 32768
#define SM_B1 65536
#define SM_RED 98304                // float sRed[3][128] = 1536
#define SMEM_BYTES (98304 + 1536 + 256)   // +256 alignment slack

struct DiagInfo {
    bool tgt;
    bool own[8];
    int dsub[8], n8d[8], dlo[8], rlA[8];
};

// Epilogue for completed subtile ctp: exp-sum + rare diag fixup.
__device__ __forceinline__ void subtile_epilogue(
    uint32_t acc[4][8][2], int ctp, float* sumReg, const DiagInfo& di,
    int row0) {
#pragma unroll
    for (int mi = 0; mi < 4; mi++)
#pragma unroll
        for (int h = 0; h < 2; h++) {
            int i = mi * 2 + h;
            __half2 e0 = h2exp2(*(__half2*)&acc[mi][0][h]);
            __half2 e1 = h2exp2(*(__half2*)&acc[mi][1][h]);
            __half2 e2 = h2exp2(*(__half2*)&acc[mi][2][h]);
            __half2 e3 = h2exp2(*(__half2*)&acc[mi][3][h]);
            __half2 e4 = h2exp2(*(__half2*)&acc[mi][4][h]);
            __half2 e5 = h2exp2(*(__half2*)&acc[mi][5][h]);
            __half2 e6 = h2exp2(*(__half2*)&acc[mi][6][h]);
            __half2 e7 = h2exp2(*(__half2*)&acc[mi][7][h]);
            __half2 t = __hadd2(__hadd2(__hadd2(e0, e1), __hadd2(e2, e3)),
                                __hadd2(__hadd2(e4, e5), __hadd2(e6, e7)));
            float2 f = __half22float2(t);
            sumReg[i] += f.x + f.y;
            if (di.own[i] && di.dsub[i] == ctp) {      // rare diag fixup
                __half2 av = *(__half2*)&acc[mi][di.n8d[i]][h];
                if (di.tgt) {
                    float aval = di.dlo[i] ? __high2float(av)
                                           : __low2float(av);
                    g_pos[row0 + di.rlA[i]] = aval * LN2F;
                } else {
                    __half2 ev = h2exp2(av);
                    sumReg[i] -= di.dlo[i] ? __high2float(ev)
                                           : __low2float(ev);
                }
            }
        }
}

__global__ void __launch_bounds__(256, 2) sim_kernel(float* __restrict__ out) {
    extern __shared__ char smem[];
    uint32_t sbraw = smem_u32(smem);
    uint32_t sb = (sbraw + 255u) & ~255u;     // 256-aligned: XOR-fold is valid
    __shared__ int sK, sLast2;
    __shared__ float wred[8];

    int tid = threadIdx.x;
    int lane = tid & 31;
    int w = tid >> 5;
    int wm = w & 1;        // M warp: rows wm*64..+63
    int wn = w >> 1;       // N warp: cols wn*64..+63 within the 256-col subtile
    int row0 = blockIdx.x * 128;
    int cg = blockIdx.y;                  // cols [cg*1024, cg*1024+1024)

    // ---- strength-reduced load addressing (affine in iteration index) ----
    uint32_t aDst = sb + SM_A + ((tid >> 4) * 256)
                  + ((((tid & 15) ^ ((tid >> 4) & 7)) & 15) << 4);
    const char* aSrc = (const char*)g_a16 + (size_t)row0 * 256
                     + (tid >> 4) * 256 + (tid & 15) * 16;
    uint32_t bDstOff = ((tid >> 3) * 128)
                     + (((tid & 7) ^ ((tid >> 3) & 7)) << 4);
    const char* bSrc00 = (const char*)g_b16 + (size_t)cg * 262144
                       + (tid >> 3) * 256 + (tid & 7) * 16;

    // ---- prologue: A (full K) + B chunk for step 0 ----
#pragma unroll
    for (int it = 0; it < 8; it++)
        CP_ASYNC16(aDst + it * 4096, aSrc + it * 4096);
#pragma unroll
    for (int it = 0; it < 8; it++)
        CP_ASYNC16(sb + SM_B0 + bDstOff + it * 4096, bSrc00 + it * 8192);
    CP_COMMIT();

    // ---- lane patterns with XOR-folded swizzle (base is 256-aligned) ----
    int rowpat = ((lane >> 3) & 1) * 8 + (lane & 7);   // A ldsm row-in-16
    int koctA = lane >> 4;                             // 0/1: k octet
    int r7 = lane & 7;                                 // swizzle key
    uint32_t baseAx0 = (sb + SM_A + (wm * 64 + rowpat) * 256)
                     ^ (uint32_t)(r7 << 4) ^ (uint32_t)(koctA << 4);
    int colpat = ((lane >> 4) & 1) * 8 + (lane & 7);   // B ldsm col-in-16
    int koctB = (lane >> 3) & 1;
    uint32_t baseBoffx = (uint32_t)((wn * 64 + colpat) * 128)
                       ^ (uint32_t)(r7 << 4) ^ (uint32_t)(koctB << 4);

    int qrow = lane >> 2;          // 0..7
    // ---- diag bookkeeping: hoisted, ct-invariant ----
    DiagInfo di;
    {
        int half = row0 >> 11;
        int cblk = cg >> 1;
        di.tgt = (cblk == 1 - half);
#pragma unroll
        for (int mi = 0; mi < 4; mi++)
#pragma unroll
            for (int h = 0; h < 2; h++) {
                int i = mi * 2 + h;
                int rl = wm * 64 + mi * 16 + qrow + 8 * h;
                di.rlA[i] = rl;
                int d = (row0 & 2047) + rl - (cg & 1) * 1024;
                di.own[i] = ((unsigned)d < 1024u) && (((d >> 6) & 3) == wn)
                          && (((d & 7) >> 1) == (lane & 3));
                di.dsub[i] = d >> 8;
                di.n8d[i] = (d & 63) >> 3;
                di.dlo[i] = d & 1;
            }
    }

    float sumReg[8];
#pragma unroll
    for (int i = 0; i < 8; i++) sumReg[i] = 0.f;

    uint32_t acc[4][8][2];   // [mi 16-row group][n8 8-col group][row half]

#pragma unroll
    for (int s = 0; s < 8; s++) {
        const int kc = s & 1;
        CP_WAIT_ALL();
        __syncthreads();               // B(s) ready; all warps done with s-1

        if (s < 7) {                   // prefetch B(s+1) chunk, overlapped
            const int ct2 = (s + 1) >> 1, kc2 = (s + 1) & 1;
            uint32_t dst = sb + (((s + 1) & 1) ? SM_B1 : SM_B0) + bDstOff;
            const char* srcp = bSrc00 + ct2 * 65536 + kc2 * 128;
#pragma unroll
            for (int it = 0; it < 8; it++)
                CP_ASYNC16(dst + it * 4096, srcp + it * 8192);
            CP_COMMIT();
        }

        // Deferred epilogue of the PREVIOUS subtile: acc still holds its
        // results (first MMA below uses zero-C). MUFU chain interleaves with
        // this step's LDSM/MMA issue via ptxas scheduling.
        if (kc == 0 && s > 0)
            subtile_epilogue(acc, (s >> 1) - 1, sumReg, di, row0);

        uint32_t baseAxk = baseAx0 ^ (uint32_t)(kc << 7);
        uint32_t baseBx = (sb + ((s & 1) ? SM_B1 : SM_B0)) + baseBoffx;

#pragma unroll
        for (int ks = 0; ks < 4; ks++) {
            uint32_t a[4][4];
#pragma unroll
            for (int mi = 0; mi < 4; mi++)
                ldsm_x4(a[mi], (baseAxk + (uint32_t)(mi * 4096))
                               ^ (uint32_t)(ks << 5));
            uint32_t b[4][4];
#pragma unroll
            for (int ns = 0; ns < 4; ns++)
                ldsm_x4(b[ns], (baseBx + (uint32_t)(ns * 2048))
                               ^ (uint32_t)(ks << 5));
            if (kc == 0 && ks == 0) {
#pragma unroll
                for (int mi = 0; mi < 4; mi++)
#pragma unroll
                    for (int ns = 0; ns < 4; ns++) {
                        mma_h16_zc(acc[mi][2 * ns + 0], a[mi], b[ns][0], b[ns][1]);
                        mma_h16_zc(acc[mi][2 * ns + 1], a[mi], b[ns][2], b[ns][3]);
                    }
            } else {
#pragma unroll
                for (int mi = 0; mi < 4; mi++)
#pragma unroll
                    for (int ns = 0; ns < 4; ns++) {
                        mma_h16(acc[mi][2 * ns + 0], a[mi], b[ns][0], b[ns][1]);
                        mma_h16(acc[mi][2 * ns + 1], a[mi], b[ns][2], b[ns][3]);
                    }
            }
        }
    }
    // final subtile's epilogue
    subtile_epilogue(acc, 3, sumReg, di, row0);

    // ---- per-row reduce: 4 col-lanes, then the 4 N warps via SMEM ----
#pragma unroll
    for (int i = 0; i < 8; i++) {
        sumReg[i] += __shfl_xor_sync(~0u, sumReg[i], 1);
        sumReg[i] += __shfl_xor_sync(~0u, sumReg[i], 2);
    }
    __syncthreads();
    if ((lane & 3) == 0 && wn > 0) {
#pragma unroll
        for (int i = 0; i < 8; i++) {
            uint32_t addr = sb + SM_RED + ((wn - 1) * 128 + di.rlA[i]) * 4;
            asm volatile("st.shared.f32 [%0], %1;" :: "r"(addr), "f"(sumReg[i]));
        }
    }
    __syncthreads();
    if ((lane & 3) == 0 && wn == 0) {
#pragma unroll
        for (int i = 0; i < 8; i++) {
            int rl = di.rlA[i];
            float v0, v1, v2;
            uint32_t a0 = sb + SM_RED + rl * 4;
            asm volatile("ld.shared.f32 %0, [%1];" : "=f"(v0) : "r"(a0));
            asm volatile("ld.shared.f32 %0, [%1];" : "=f"(v1) : "r"(a0 + 512));
            asm volatile("ld.shared.f32 %0, [%1];" : "=f"(v2) : "r"(a0 + 1024));
            int row = row0 + rl;
            g_S[row * 8 + cg] = sumReg[i] + v0 + v1 + v2;
        }
    }

    // ---- last-16-CTA finalize (256 CTAs co-resident wave) ----
    __threadfence();
    __syncthreads();
    if (tid == 0) sK = (int)atomicAdd(&g_cnt, 1u);
    __syncthreads();
    int k = sK;
    if (k >= 240) {
        if (k == 255 && tid == 0) atomicExch(&g_flag, 1u);
        if (tid == 0) while (atomicAdd(&g_flag, 0u) == 0u) { }
        __syncthreads();
        __threadfence();
        int row = (k - 240) * 256 + tid;
        const float4* s4 = (const float4*)(g_S + row * 8);
        float4 x0 = s4[0], x1 = s4[1];
        float S = (x0.x + x0.y) + (x0.z + x0.w) + (x1.x + x1.y) + (x1.z + x1.w);
        float local = logf(S) - g_pos[row];
#pragma unroll
        for (int off = 16; off; off >>= 1) local += __shfl_xor_sync(~0u, local, off);
        if (lane == 0) wred[tid >> 5] = local;
        __syncthreads();
        if (tid == 0) {
            float t = 0.f;
#pragma unroll
            for (int q = 0; q < 8; q++) t += wred[q];
            g_fin[k - 240] = t;
            __threadfence();
            int k2 = (int)atomicAdd(&g_cnt2, 1u);
            sLast2 = (k2 == 15);
        }
        __syncthreads();
        if (sLast2 && tid == 0) {
            __threadfence();
            float t = 0.f;
#pragma unroll
            for (int q = 0; q < 16; q++) t += g_fin[q];
            out[0] = t / 4096.f;
            g_cnt = 0; g_cnt2 = 0; g_flag = 0;    // reset for graph replay
        }
    }
}

// ---------------------------------------------------------------------------
extern "C" void kernel_launch(void* const* d_in, const int* in_sizes, int n_in,
                              void* d_out, int out_size) {
    const float* a1 = (const float*)d_in[0];
    const float* a2 = (const float*)d_in[1];
    const float* a3 = (const float*)d_in[2];
    const float* a4 = (const float*)d_in[3];

    normalize_kernel<<<1024, 256>>>(a1, a2, a3, a4);

    cudaFuncSetAttribute(sim_kernel, cudaFuncAttributeMaxDynamicSharedMemorySize,
                         SMEM_BYTES);
    dim3 grid(32, 8);
    sim_kernel<<<grid, 256, SMEM_BYTES>>>((float*)d_out);
}